// round 3
// baseline (speedup 1.0000x reference)
#include <cuda_runtime.h>
#include <cuda_bf16.h>
#include <math.h>

// ---------------------------------------------------------------------------
// GAT 3-layer pipeline (GATConv heads=1 with edge features, PyG semantics).
// Layers: (128->128, relu), (128->128, relu), (128->64).
// h = x@W ; alpha=leakyrelu((h@a_s)[src]+(h@a_d)[dst]+ea.(We@ae));
// segment softmax over dst; out[dst] = sum(w*h[src]) + b.
// Self-loop edge-attr = mean of incoming attrs; linear => scalar = segsum/deg.
// edge_index dtype (int32 vs int64) auto-detected on device.
// ---------------------------------------------------------------------------

#define MAXN 50048
#define MAXE 600064
#define MAXET (MAXE + MAXN)

__device__ float g_h[MAXN * 128];
__device__ float g_bufA[MAXN * 128];
__device__ float g_bufB[MAXN * 128];
__device__ float g_ss[MAXN];
__device__ float g_sd[MAXN];
__device__ float g_ee[3 * MAXET];
__device__ float g_eesum[3 * MAXN];
__device__ int   g_deg[MAXN];
__device__ int   g_off[MAXN + 1];
__device__ int   g_cur[MAXN];
__device__ int   g_csrc[MAXET];
__device__ int   g_ceid[MAXET];
__device__ float g_v[24];
__device__ int   g_is64;               // 1 if edge_index is int64, 0 if int32

// Index accessor: element position i in the flat (2,E) edge_index buffer.
__device__ __forceinline__ int get_idx(const void* ei, int i) {
    if (g_is64) return (int)((const long long*)ei)[i];
    return ((const int*)ei)[i];
}

// ---------------------------------------------------------------------------
__global__ void detect_kernel(const int* __restrict__ w, int forced) {
    if (forced >= 0) { g_is64 = forced; return; }
    // int64 little-endian indices < 2^31 have zero high words at odd positions.
    int is64 = 1;
    for (int i = 1; i < 32; i += 2)
        if (w[i] != 0) is64 = 0;
    g_is64 = is64;
}

__global__ void zero_kernel(int n) {
    int i = blockIdx.x * blockDim.x + threadIdx.x;
    int total = n * 3;
    for (int t = i; t < total; t += gridDim.x * blockDim.x) {
        g_eesum[t] = 0.f;
        if (t < n) g_deg[t] = 0;
    }
}

__global__ void count_deg_kernel(const void* __restrict__ ei, int E, int n) {
    int e = blockIdx.x * blockDim.x + threadIdx.x;
    if (e >= E) return;
    int d = get_idx(ei, E + e);
    if ((unsigned)d < (unsigned)n) atomicAdd(&g_deg[d], 1);
}

__global__ void compute_v_kernel(const float* We0, const float* ae0,
                                 const float* We1, const float* ae1,
                                 const float* We2, const float* ae2) {
    int t = threadIdx.x;
    if (t >= 24) return;
    int l = t / 8, j = t % 8;
    const float* We = (l == 0) ? We0 : (l == 1) ? We1 : We2;
    const float* ae = (l == 0) ? ae0 : (l == 1) ? ae1 : ae2;
    int C = (l == 2) ? 64 : 128;
    float s = 0.f;
    for (int c = 0; c < C; c++) s += We[j * C + c] * ae[c];
    g_v[l * 8 + j] = s;
}

__global__ void edge_ee_kernel(const float* __restrict__ ea,
                               const void* __restrict__ ei,
                               int E, int Etot, int n) {
    int e = blockIdx.x * blockDim.x + threadIdx.x;
    if (e >= E) return;
    float a[8];
#pragma unroll
    for (int j = 0; j < 8; j++) a[j] = ea[e * 8 + j];
    int d = get_idx(ei, E + e);
    bool ok = (unsigned)d < (unsigned)n;
#pragma unroll
    for (int l = 0; l < 3; l++) {
        float s = 0.f;
#pragma unroll
        for (int j = 0; j < 8; j++) s += a[j] * g_v[l * 8 + j];
        g_ee[l * Etot + e] = s;
        if (ok) atomicAdd(&g_eesum[l * n + d], s);
    }
}

// single-block chunked exclusive scan of (deg[i]+1)
__global__ void scan_kernel(int n) {
    __shared__ int sh[1024];
    __shared__ int carry;
    if (threadIdx.x == 0) carry = 0;
    __syncthreads();
    for (int base = 0; base < n; base += 1024) {
        int i = base + threadIdx.x;
        int val = (i < n) ? (g_deg[i] + 1) : 0;
        sh[threadIdx.x] = val;
        __syncthreads();
        for (int o = 1; o < 1024; o <<= 1) {
            int t = (threadIdx.x >= o) ? sh[threadIdx.x - o] : 0;
            __syncthreads();
            sh[threadIdx.x] += t;
            __syncthreads();
        }
        int excl = carry + sh[threadIdx.x] - val;
        if (i < n) { g_off[i] = excl; g_cur[i] = excl; }
        __syncthreads();
        if (threadIdx.x == 1023) carry += sh[1023];
        __syncthreads();
    }
    if (threadIdx.x == 0) g_off[n] = carry;
}

__global__ void selfloop_ee_kernel(int E, int Etot, int n) {
    int i = blockIdx.x * blockDim.x + threadIdx.x;
    if (i >= n) return;
    float invd = 1.f / fmaxf((float)g_deg[i], 1.f);
#pragma unroll
    for (int l = 0; l < 3; l++)
        g_ee[l * Etot + E + i] = g_eesum[l * n + i] * invd;
}

__global__ void csr_fill_kernel(const void* __restrict__ ei, int E, int n) {
    int e = blockIdx.x * blockDim.x + threadIdx.x;
    if (e >= E + n) return;
    int s, d;
    if (e < E) { s = get_idx(ei, e); d = get_idx(ei, E + e); }
    else       { s = d = e - E; }
    if ((unsigned)d >= (unsigned)n || (unsigned)s >= (unsigned)n) return;
    int p = atomicAdd(&g_cur[d], 1);
    if (p < MAXET) { g_csrc[p] = s; g_ceid[p] = e; }
}

// ---------------------------------------------------------------------------
// Tiled fp32 GEMM: C[M,Cn] = A[M,K] @ B[K,Cn].  64x64 tile, 256 thr, 4x4/thr.
__global__ void sgemm_kernel(const float* __restrict__ A, const float* __restrict__ B,
                             float* __restrict__ Cm, int M, int K, int Cn) {
    const int BM = 64, BN = 64, BK = 16;
    __shared__ float As[BK][BM];
    __shared__ float Bs[BK][BN];
    int tx = threadIdx.x % 16, ty = threadIdx.x / 16;
    int row0 = blockIdx.y * BM, col0 = blockIdx.x * BN;
    float acc[4][4] = {};
    for (int kt = 0; kt < K; kt += BK) {
        for (int i = threadIdx.x; i < BM * BK; i += 256) {
            int m = i / BK, k = i % BK;
            int gr = row0 + m;
            As[k][m] = (gr < M) ? A[(size_t)gr * K + kt + k] : 0.f;
        }
        for (int i = threadIdx.x; i < BK * BN; i += 256) {
            int k = i / BN, nn = i % BN;
            Bs[k][nn] = B[(size_t)(kt + k) * Cn + col0 + nn];
        }
        __syncthreads();
#pragma unroll
        for (int k = 0; k < BK; k++) {
            float a[4], bb[4];
#pragma unroll
            for (int i = 0; i < 4; i++) a[i] = As[k][ty * 4 + i];
#pragma unroll
            for (int j = 0; j < 4; j++) bb[j] = Bs[k][tx * 4 + j];
#pragma unroll
            for (int i = 0; i < 4; i++)
#pragma unroll
                for (int j = 0; j < 4; j++) acc[i][j] += a[i] * bb[j];
        }
        __syncthreads();
    }
    for (int i = 0; i < 4; i++) {
        int r = row0 + ty * 4 + i;
        if (r >= M) break;
        for (int j = 0; j < 4; j++)
            Cm[(size_t)r * Cn + col0 + tx * 4 + j] = acc[i][j];
    }
}

// ---------------------------------------------------------------------------
__global__ void scores_kernel(const float* __restrict__ as_,
                              const float* __restrict__ ad_, int n, int C) {
    int w = (blockIdx.x * blockDim.x + threadIdx.x) >> 5;
    int lane = threadIdx.x & 31;
    if (w >= n) return;
    float s1 = 0.f, s2 = 0.f;
    for (int c = lane; c < C; c += 32) {
        float v = g_h[(size_t)w * C + c];
        s1 += v * as_[c];
        s2 += v * ad_[c];
    }
#pragma unroll
    for (int o = 16; o; o >>= 1) {
        s1 += __shfl_xor_sync(0xffffffffu, s1, o);
        s2 += __shfl_xor_sync(0xffffffffu, s2, o);
    }
    if (lane == 0) { g_ss[w] = s1; g_sd[w] = s2; }
}

// ---------------------------------------------------------------------------
// Warp-per-dst-node softmax + aggregation.  C in {64,128}.
template <int C>
__global__ void aggregate_kernel(int layer, int Etot,
                                 const float* __restrict__ bias,
                                 float* __restrict__ out,
                                 int n, int do_relu) {
    const int KC = C / 32;
    const float* ee = g_ee + (size_t)layer * Etot;
    int node = blockIdx.x * (blockDim.x >> 5) + (threadIdx.x >> 5);
    int lane = threadIdx.x & 31;
    if (node >= n) return;
    int e0 = g_off[node], e1 = g_off[node + 1];
    float sdn = g_sd[node];

    // pass 1: max
    float m = -INFINITY;
    for (int j = e0 + lane; j < e1; j += 32) {
        float a = g_ss[g_csrc[j]] + sdn + ee[g_ceid[j]];
        a = (a > 0.f) ? a : 0.2f * a;
        m = fmaxf(m, a);
    }
#pragma unroll
    for (int o = 16; o; o >>= 1) m = fmaxf(m, __shfl_xor_sync(0xffffffffu, m, o));

    // pass 2: exp-weighted accumulate
    float acc[KC];
#pragma unroll
    for (int q = 0; q < KC; q++) acc[q] = 0.f;
    float denom = 0.f;
    for (int jb = e0; jb < e1; jb += 32) {
        int j = jb + lane;
        float ex = 0.f;
        int s = 0;
        if (j < e1) {
            s = g_csrc[j];
            float a = g_ss[s] + sdn + ee[g_ceid[j]];
            a = (a > 0.f) ? a : 0.2f * a;
            ex = expf(a - m);
            denom += ex;
        }
        int cnt = min(32, e1 - jb);
        for (int k = 0; k < cnt; k++) {
            float exk = __shfl_sync(0xffffffffu, ex, k);
            int sk = __shfl_sync(0xffffffffu, s, k);
            const float* hp = g_h + (size_t)sk * C + lane;
#pragma unroll
            for (int q = 0; q < KC; q++) acc[q] += exk * hp[q * 32];
        }
    }
#pragma unroll
    for (int o = 16; o; o >>= 1) denom += __shfl_xor_sync(0xffffffffu, denom, o);
    float inv = 1.f / (denom + 1e-16f);
#pragma unroll
    for (int q = 0; q < KC; q++) {
        int c = q * 32 + lane;
        float v = acc[q] * inv + bias[c];
        if (do_relu) v = fmaxf(v, 0.f);
        out[(size_t)node * C + c] = v;
    }
}

extern "C" void kernel_launch(void* const* d_in, const int* in_sizes, int n_in,
                              void* d_out, int out_size) {
    const float* x      = (const float*)d_in[0];
    const void*  ei     = d_in[1];
    const float* ea     = (const float*)d_in[2];
    const float* W[3]  = {(const float*)d_in[3],  (const float*)d_in[9],  (const float*)d_in[15]};
    const float* As[3] = {(const float*)d_in[4],  (const float*)d_in[10], (const float*)d_in[16]};
    const float* Ad[3] = {(const float*)d_in[5],  (const float*)d_in[11], (const float*)d_in[17]};
    const float* We[3] = {(const float*)d_in[6],  (const float*)d_in[12], (const float*)d_in[18]};
    const float* Ae[3] = {(const float*)d_in[7],  (const float*)d_in[13], (const float*)d_in[19]};
    const float* Bb[3] = {(const float*)d_in[8],  (const float*)d_in[14], (const float*)d_in[20]};

    int N = in_sizes[0] / 128;
    int E = in_sizes[2] / 8;          // from edge_attr [E,8] -- dtype-invariant
    int Etot = E + N;
    // If the edge_index buffer reports 4*E elements, it is int64 counted as
    // int32 words -> force int64 mode; if 2*E, auto-detect on device.
    int forced = (in_sizes[1] == 4 * E) ? 1 : -1;

    static float* h = nullptr;
    static float* bufA = nullptr;
    static float* bufB = nullptr;
    if (!h) {
        cudaGetSymbolAddress((void**)&h,    g_h);
        cudaGetSymbolAddress((void**)&bufA, g_bufA);
        cudaGetSymbolAddress((void**)&bufB, g_bufB);
    }

    // ---- preprocessing ----
    detect_kernel<<<1, 1>>>((const int*)ei, forced);
    zero_kernel<<<(3 * N + 255) / 256, 256>>>(N);
    count_deg_kernel<<<(E + 255) / 256, 256>>>(ei, E, N);
    compute_v_kernel<<<1, 32>>>(We[0], Ae[0], We[1], Ae[1], We[2], Ae[2]);
    edge_ee_kernel<<<(E + 255) / 256, 256>>>(ea, ei, E, Etot, N);
    scan_kernel<<<1, 1024>>>(N);
    selfloop_ee_kernel<<<(N + 255) / 256, 256>>>(E, Etot, N);
    csr_fill_kernel<<<(Etot + 255) / 256, 256>>>(ei, E, N);

    // ---- layers ----
    const float* xin = x;
    float* outs[3] = {bufA, bufB, (float*)d_out};
    int Cs[3] = {128, 128, 64};
    for (int l = 0; l < 3; l++) {
        int C = Cs[l];
        dim3 gg(C / 64, (N + 63) / 64);
        sgemm_kernel<<<gg, 256>>>(xin, W[l], h, N, 128, C);
        scores_kernel<<<(N * 32 + 255) / 256, 256>>>(As[l], Ad[l], N, C);
        int nb = (N + 7) / 8;
        if (C == 128)
            aggregate_kernel<128><<<nb, 256>>>(l, Etot, Bb[l], outs[l], N, l < 2);
        else
            aggregate_kernel<64><<<nb, 256>>>(l, Etot, Bb[l], outs[l], N, l < 2);
        xin = outs[l];
    }
}

// round 4
// speedup vs baseline: 1.3823x; 1.3823x over previous
#include <cuda_runtime.h>
#include <cuda_bf16.h>
#include <math.h>

// ---------------------------------------------------------------------------
// GAT 3-layer pipeline (GATConv heads=1 + edge features, PyG semantics).
// R4: fused launches (17->10), 128-wide fused GEMM+scores, online-softmax
// aggregation.
// ---------------------------------------------------------------------------

#define MAXN 50048
#define MAXE 600064
#define MAXET (MAXE + MAXN)

__device__ float g_h[MAXN * 128];
__device__ float g_bufA[MAXN * 128];
__device__ float g_bufB[MAXN * 128];
__device__ float g_ss[MAXN];
__device__ float g_sd[MAXN];
__device__ float g_ee[3 * MAXET];
__device__ float g_eesum[3 * MAXN];
__device__ int   g_deg[MAXN];
__device__ int   g_off[MAXN + 1];
__device__ int   g_cur[MAXN];
__device__ int   g_csrc[MAXET];
__device__ int   g_ceid[MAXET];
__device__ float g_v[24];
__device__ int   g_is64;

__device__ __forceinline__ int get_idx(const void* ei, int i) {
    if (g_is64) return (int)((const long long*)ei)[i];
    return ((const int*)ei)[i];
}

// ---------------------------------------------------------------------------
// K1: zero deg/eesum + dtype detect + We@ae vectors, all in one kernel.
__global__ void init_kernel(const int* __restrict__ eiw, int forced,
                            const float* We0, const float* ae0,
                            const float* We1, const float* ae1,
                            const float* We2, const float* ae2, int n) {
    int i = blockIdx.x * blockDim.x + threadIdx.x;
    int total = n * 3;
    for (int t = i; t < total; t += gridDim.x * blockDim.x) {
        g_eesum[t] = 0.f;
        if (t < n) g_deg[t] = 0;
    }
    if (blockIdx.x == 0) {
        if (threadIdx.x == 0) {
            if (forced >= 0) g_is64 = forced;
            else {
                int is64 = 1;
                for (int j = 1; j < 32; j += 2)
                    if (eiw[j] != 0) is64 = 0;
                g_is64 = is64;
            }
        }
        int t = (int)threadIdx.x - 32;
        if (t >= 0 && t < 24) {
            int l = t / 8, j = t % 8;
            const float* We = (l == 0) ? We0 : (l == 1) ? We1 : We2;
            const float* ae = (l == 0) ? ae0 : (l == 1) ? ae1 : ae2;
            int C = (l == 2) ? 64 : 128;
            float s = 0.f;
            for (int c = 0; c < C; c++) s += We[j * C + c] * ae[c];
            g_v[l * 8 + j] = s;
        }
    }
}

// K2: per-edge scalars for 3 layers + eesum + degree count (fused).
__global__ void edge_kernel(const float* __restrict__ ea,
                            const void* __restrict__ ei,
                            int E, int Etot, int n) {
    int e = blockIdx.x * blockDim.x + threadIdx.x;
    if (e >= E) return;
    float a[8];
#pragma unroll
    for (int j = 0; j < 8; j++) a[j] = ea[e * 8 + j];
    int d = get_idx(ei, E + e);
    bool ok = (unsigned)d < (unsigned)n;
    if (ok) atomicAdd(&g_deg[d], 1);
#pragma unroll
    for (int l = 0; l < 3; l++) {
        float s = 0.f;
#pragma unroll
        for (int j = 0; j < 8; j++) s += a[j] * g_v[l * 8 + j];
        g_ee[l * Etot + e] = s;
        if (ok) atomicAdd(&g_eesum[l * n + d], s);
    }
}

// K3: single-block segmented scan of (deg+1): each thread owns a contiguous
// chunk; warp-shuffle block scan of the 1024 thread sums.
__global__ void scan_kernel(int n) {
    __shared__ int wsum[32];
    int tid = threadIdx.x;
    int per = (n + 1023) / 1024;
    int st = tid * per;
    int en = min(st + per, n);
    int s = 0;
    for (int i = st; i < en; i++) s += g_deg[i] + 1;
    int lane = tid & 31, wid = tid >> 5;
    int v = s;
#pragma unroll
    for (int o = 1; o < 32; o <<= 1) {
        int t = __shfl_up_sync(0xffffffffu, v, o);
        if (lane >= o) v += t;
    }
    if (lane == 31) wsum[wid] = v;
    __syncthreads();
    if (wid == 0) {
        int w = wsum[lane];
#pragma unroll
        for (int o = 1; o < 32; o <<= 1) {
            int t = __shfl_up_sync(0xffffffffu, w, o);
            if (lane >= o) w += t;
        }
        wsum[lane] = w;
    }
    __syncthreads();
    int base = v - s + ((wid > 0) ? wsum[wid - 1] : 0);
    for (int i = st; i < en; i++) {
        g_off[i] = base;
        g_cur[i] = base;
        base += g_deg[i] + 1;
    }
    if (tid == 1023) g_off[n] = base;
}

// K4: CSR fill (edges + self loops) + self-loop ee scalars (fused).
__global__ void fill_kernel(const void* __restrict__ ei, int E, int Etot, int n) {
    int e = blockIdx.x * blockDim.x + threadIdx.x;
    if (e >= E + n) return;
    if (e < E) {
        int s = get_idx(ei, e);
        int d = get_idx(ei, E + e);
        if ((unsigned)d >= (unsigned)n || (unsigned)s >= (unsigned)n) return;
        int p = atomicAdd(&g_cur[d], 1);
        if (p < MAXET) { g_csrc[p] = s; g_ceid[p] = e; }
    } else {
        int i = e - E;
        int p = atomicAdd(&g_cur[i], 1);
        if (p < MAXET) { g_csrc[p] = i; g_ceid[p] = e; }
        float invd = 1.f / fmaxf((float)g_deg[i], 1.f);
#pragma unroll
        for (int l = 0; l < 3; l++)
            g_ee[l * Etot + E + i] = g_eesum[l * n + i] * invd;
    }
}

// ---------------------------------------------------------------------------
// Fused GEMM + attention scores. H[M,BN] = A[M,128] @ B[128,BN];
// ss = H@as, sd = H@ad computed in-register in the epilogue.
// BM=128, BK=32, 256 threads, per-thread (2x4)x(NJx4) micro-tile.
template <int BN>
__global__ void __launch_bounds__(256, 2)
sgemm_fused(const float* __restrict__ A, const float* __restrict__ B,
            const float* __restrict__ as_, const float* __restrict__ ad_,
            float* __restrict__ H, int M) {
    const int BM = 128, BK = 32, K = 128;
    const int NJ = (BN == 128) ? 2 : 1;
    __shared__ float As[BK][BM];
    __shared__ float Bs[BK][BN];
    int tid = threadIdx.x;
    int tx = tid & 15, ty = tid >> 4;
    int row0 = blockIdx.x * BM;
    float acc[2][4][NJ][4];
#pragma unroll
    for (int ri = 0; ri < 2; ri++)
#pragma unroll
        for (int i = 0; i < 4; i++)
#pragma unroll
            for (int cj = 0; cj < NJ; cj++)
#pragma unroll
                for (int j = 0; j < 4; j++) acc[ri][i][cj][j] = 0.f;

    for (int kt = 0; kt < K; kt += BK) {
        // A tile: 128 rows x 32 k, float4 loads along k, transposed store.
#pragma unroll
        for (int t = 0; t < 4; t++) {
            int f = tid + t * 256;
            int r = f >> 3, k4 = (f & 7) << 2;
            float4 v = make_float4(0.f, 0.f, 0.f, 0.f);
            int gr = row0 + r;
            if (gr < M) v = *(const float4*)(A + (size_t)gr * K + kt + k4);
            As[k4 + 0][r] = v.x; As[k4 + 1][r] = v.y;
            As[k4 + 2][r] = v.z; As[k4 + 3][r] = v.w;
        }
        // B tile: 32 k x BN cols.
#pragma unroll
        for (int t = 0; t < (BN * BK) / (256 * 4); t++) {
            int f = tid + t * 256;
            int k = f / (BN / 4);
            int c4 = (f % (BN / 4)) * 4;
            *(float4*)&Bs[k][c4] = *(const float4*)(B + (size_t)(kt + k) * BN + c4);
        }
        __syncthreads();
#pragma unroll
        for (int k = 0; k < BK; k++) {
            float4 a0 = *(const float4*)&As[k][ty * 4];
            float4 a1 = *(const float4*)&As[k][64 + ty * 4];
            float av[2][4] = {{a0.x, a0.y, a0.z, a0.w}, {a1.x, a1.y, a1.z, a1.w}};
            float bv[NJ][4];
            float4 b0 = *(const float4*)&Bs[k][tx * 4];
            bv[0][0] = b0.x; bv[0][1] = b0.y; bv[0][2] = b0.z; bv[0][3] = b0.w;
            if (NJ == 2) {
                float4 b1 = *(const float4*)&Bs[k][64 + tx * 4];
                bv[1][0] = b1.x; bv[1][1] = b1.y; bv[1][2] = b1.z; bv[1][3] = b1.w;
            }
#pragma unroll
            for (int ri = 0; ri < 2; ri++)
#pragma unroll
                for (int i = 0; i < 4; i++)
#pragma unroll
                    for (int cj = 0; cj < NJ; cj++)
#pragma unroll
                        for (int j = 0; j < 4; j++)
                            acc[ri][i][cj][j] += av[ri][i] * bv[cj][j];
        }
        __syncthreads();
    }

    // attention-vector slices for this thread's columns
    float asv[NJ][4], adv[NJ][4];
#pragma unroll
    for (int cj = 0; cj < NJ; cj++)
#pragma unroll
        for (int j = 0; j < 4; j++) {
            int c = cj * 64 + tx * 4 + j;
            asv[cj][j] = as_[c];
            adv[cj][j] = ad_[c];
        }

#pragma unroll
    for (int ri = 0; ri < 2; ri++)
#pragma unroll
        for (int i = 0; i < 4; i++) {
            int r = row0 + ri * 64 + ty * 4 + i;
            float s1 = 0.f, s2 = 0.f;
#pragma unroll
            for (int cj = 0; cj < NJ; cj++) {
#pragma unroll
                for (int j = 0; j < 4; j++) {
                    s1 += acc[ri][i][cj][j] * asv[cj][j];
                    s2 += acc[ri][i][cj][j] * adv[cj][j];
                }
            }
#pragma unroll
            for (int o = 1; o < 16; o <<= 1) {
                s1 += __shfl_xor_sync(0xffffffffu, s1, o);
                s2 += __shfl_xor_sync(0xffffffffu, s2, o);
            }
            if (r < M) {
#pragma unroll
                for (int cj = 0; cj < NJ; cj++)
                    *(float4*)&H[(size_t)r * BN + cj * 64 + tx * 4] =
                        make_float4(acc[ri][i][cj][0], acc[ri][i][cj][1],
                                    acc[ri][i][cj][2], acc[ri][i][cj][3]);
                if (tx == 0) { g_ss[r] = s1; g_sd[r] = s2; }
            }
        }
}

// ---------------------------------------------------------------------------
// Warp-per-dst-node ONLINE softmax + aggregation.
template <int C>
__global__ void aggregate_kernel(int layer, int Etot,
                                 const float* __restrict__ bias,
                                 float* __restrict__ out,
                                 int n, int do_relu) {
    const int KC = C / 32;
    const float* ee = g_ee + (size_t)layer * Etot;
    int node = blockIdx.x * (blockDim.x >> 5) + (threadIdx.x >> 5);
    int lane = threadIdx.x & 31;
    if (node >= n) return;
    int e0 = g_off[node], e1 = g_off[node + 1];
    float sdn = g_sd[node];

    float m = -INFINITY, denom = 0.f;
    float acc[KC];
#pragma unroll
    for (int q = 0; q < KC; q++) acc[q] = 0.f;

    for (int jb = e0; jb < e1; jb += 32) {
        int j = jb + lane;
        float a = -INFINITY;
        int s = 0;
        if (j < e1) {
            s = g_csrc[j];
            a = g_ss[s] + sdn + ee[g_ceid[j]];
            a = (a > 0.f) ? a : 0.2f * a;
        }
        // block max
        float bm = a;
#pragma unroll
        for (int o = 16; o; o >>= 1) bm = fmaxf(bm, __shfl_xor_sync(0xffffffffu, bm, o));
        float newm = fmaxf(m, bm);
        float scale = __expf(m - newm);   // m=-inf first iter -> 0
        denom *= scale;
#pragma unroll
        for (int q = 0; q < KC; q++) acc[q] *= scale;
        m = newm;
        float ex = (j < e1) ? __expf(a - m) : 0.f;
        denom += ex;
        int cnt = min(32, e1 - jb);
        for (int k = 0; k < cnt; k++) {
            float exk = __shfl_sync(0xffffffffu, ex, k);
            int sk = __shfl_sync(0xffffffffu, s, k);
            const float* hp = g_h + (size_t)sk * C + lane;
#pragma unroll
            for (int q = 0; q < KC; q++) acc[q] += exk * hp[q * 32];
        }
    }
#pragma unroll
    for (int o = 16; o; o >>= 1) denom += __shfl_xor_sync(0xffffffffu, denom, o);
    float inv = 1.f / (denom + 1e-16f);
#pragma unroll
    for (int q = 0; q < KC; q++) {
        int c = q * 32 + lane;
        float v = acc[q] * inv + bias[c];
        if (do_relu) v = fmaxf(v, 0.f);
        out[(size_t)node * C + c] = v;
    }
}

extern "C" void kernel_launch(void* const* d_in, const int* in_sizes, int n_in,
                              void* d_out, int out_size) {
    const float* x      = (const float*)d_in[0];
    const void*  ei     = d_in[1];
    const float* ea     = (const float*)d_in[2];
    const float* W[3]  = {(const float*)d_in[3],  (const float*)d_in[9],  (const float*)d_in[15]};
    const float* As[3] = {(const float*)d_in[4],  (const float*)d_in[10], (const float*)d_in[16]};
    const float* Ad[3] = {(const float*)d_in[5],  (const float*)d_in[11], (const float*)d_in[17]};
    const float* We[3] = {(const float*)d_in[6],  (const float*)d_in[12], (const float*)d_in[18]};
    const float* Ae[3] = {(const float*)d_in[7],  (const float*)d_in[13], (const float*)d_in[19]};
    const float* Bb[3] = {(const float*)d_in[8],  (const float*)d_in[14], (const float*)d_in[20]};

    int N = in_sizes[0] / 128;
    int E = in_sizes[2] / 8;
    int Etot = E + N;
    int forced = (in_sizes[1] == 4 * E) ? 1 : -1;

    static float* h = nullptr;
    static float* bufA = nullptr;
    static float* bufB = nullptr;
    if (!h) {
        cudaGetSymbolAddress((void**)&h,    g_h);
        cudaGetSymbolAddress((void**)&bufA, g_bufA);
        cudaGetSymbolAddress((void**)&bufB, g_bufB);
    }

    // ---- preprocessing: 4 launches ----
    init_kernel<<<(3 * N + 255) / 256, 256>>>((const int*)ei, forced,
                                              We[0], Ae[0], We[1], Ae[1], We[2], Ae[2], N);
    edge_kernel<<<(E + 255) / 256, 256>>>(ea, ei, E, Etot, N);
    scan_kernel<<<1, 1024>>>(N);
    fill_kernel<<<(Etot + 255) / 256, 256>>>(ei, E, Etot, N);

    // ---- layers: 2 launches each ----
    const float* xin = x;
    float* outs[3] = {bufA, bufB, (float*)d_out};
    for (int l = 0; l < 3; l++) {
        int C = (l == 2) ? 64 : 128;
        int gb = (N + 127) / 128;
        if (C == 128)
            sgemm_fused<128><<<gb, 256>>>(xin, W[l], As[l], Ad[l], h, N);
        else
            sgemm_fused<64><<<gb, 256>>>(xin, W[l], As[l], Ad[l], h, N);
        int nb = (N + 7) / 8;
        if (C == 128)
            aggregate_kernel<128><<<nb, 256>>>(l, Etot, Bb[l], outs[l], N, 1);
        else
            aggregate_kernel<64><<<nb, 256>>>(l, Etot, Bb[l], outs[l], N, 0);
        xin = outs[l];
    }
}

// round 5
// speedup vs baseline: 1.5529x; 1.1235x over previous
#include <cuda_runtime.h>
#include <cuda_bf16.h>
#include <math.h>

// ---------------------------------------------------------------------------
// GAT 3-layer pipeline. R5: tf32 tensor-core GEMM (mma.m16n8k4), float4
// aggregation gather, CSR-ordered edge scalars (no ceid indirection).
// ---------------------------------------------------------------------------

#define MAXN 50048
#define MAXE 600064
#define MAXET (MAXE + MAXN)

__device__ float g_h[MAXN * 128];
__device__ float g_bufA[MAXN * 128];
__device__ float g_bufB[MAXN * 128];
__device__ float g_ss[MAXN];
__device__ float g_sd[MAXN];
__device__ float g_ee[3 * MAXET];      // per-edge scalar, edge order (pre)
__device__ float g_cee[3 * MAXET];     // per-edge scalar, CSR order
__device__ float g_eesum[3 * MAXN];
__device__ int   g_deg[MAXN];
__device__ int   g_off[MAXN + 1];
__device__ int   g_cur[MAXN];
__device__ int   g_csrc[MAXET];
__device__ float g_v[24];
__device__ int   g_is64;

__device__ __forceinline__ int get_idx(const void* ei, int i) {
    if (g_is64) return (int)((const long long*)ei)[i];
    return ((const int*)ei)[i];
}

__device__ __forceinline__ unsigned f2tf32(float x) {
    unsigned u;
    asm("cvt.rna.tf32.f32 %0, %1;" : "=r"(u) : "f"(x));
    return u;
}

__device__ __forceinline__ void mma_tf32_k4(float4& c, unsigned a0, unsigned a1,
                                            unsigned b0) {
    asm volatile(
        "mma.sync.aligned.m16n8k4.row.col.f32.tf32.tf32.f32 "
        "{%0,%1,%2,%3}, {%4,%5}, {%6}, {%0,%1,%2,%3};"
        : "+f"(c.x), "+f"(c.y), "+f"(c.z), "+f"(c.w)
        : "r"(a0), "r"(a1), "r"(b0));
}

// ---------------------------------------------------------------------------
// K1: zero deg/eesum + dtype detect + We@ae vectors.
__global__ void init_kernel(const int* __restrict__ eiw, int forced,
                            const float* We0, const float* ae0,
                            const float* We1, const float* ae1,
                            const float* We2, const float* ae2, int n) {
    int i = blockIdx.x * blockDim.x + threadIdx.x;
    int total = n * 3;
    for (int t = i; t < total; t += gridDim.x * blockDim.x) {
        g_eesum[t] = 0.f;
        if (t < n) g_deg[t] = 0;
    }
    if (blockIdx.x == 0) {
        if (threadIdx.x == 0) {
            if (forced >= 0) g_is64 = forced;
            else {
                int is64 = 1;
                for (int j = 1; j < 32; j += 2)
                    if (eiw[j] != 0) is64 = 0;
                g_is64 = is64;
            }
        }
        int t = (int)threadIdx.x - 32;
        if (t >= 0 && t < 24) {
            int l = t / 8, j = t % 8;
            const float* We = (l == 0) ? We0 : (l == 1) ? We1 : We2;
            const float* ae = (l == 0) ? ae0 : (l == 1) ? ae1 : ae2;
            int C = (l == 2) ? 64 : 128;
            float s = 0.f;
            for (int c = 0; c < C; c++) s += We[j * C + c] * ae[c];
            g_v[l * 8 + j] = s;
        }
    }
}

// K2: per-edge scalars (3 layers) + eesum + degree count.
__global__ void edge_kernel(const float* __restrict__ ea,
                            const void* __restrict__ ei,
                            int E, int Etot, int n) {
    int e = blockIdx.x * blockDim.x + threadIdx.x;
    if (e >= E) return;
    float a[8];
#pragma unroll
    for (int j = 0; j < 8; j++) a[j] = ea[e * 8 + j];
    int d = get_idx(ei, E + e);
    bool ok = (unsigned)d < (unsigned)n;
    if (ok) atomicAdd(&g_deg[d], 1);
#pragma unroll
    for (int l = 0; l < 3; l++) {
        float s = 0.f;
#pragma unroll
        for (int j = 0; j < 8; j++) s += a[j] * g_v[l * 8 + j];
        g_ee[l * Etot + e] = s;
        if (ok) atomicAdd(&g_eesum[l * n + d], s);
    }
}

// K3: single-block scan of (deg+1).
__global__ void scan_kernel(int n) {
    __shared__ int wsum[32];
    int tid = threadIdx.x;
    int per = (n + 1023) / 1024;
    int st = tid * per;
    int en = min(st + per, n);
    int s = 0;
    for (int i = st; i < en; i++) s += g_deg[i] + 1;
    int lane = tid & 31, wid = tid >> 5;
    int v = s;
#pragma unroll
    for (int o = 1; o < 32; o <<= 1) {
        int t = __shfl_up_sync(0xffffffffu, v, o);
        if (lane >= o) v += t;
    }
    if (lane == 31) wsum[wid] = v;
    __syncthreads();
    if (wid == 0) {
        int w = wsum[lane];
#pragma unroll
        for (int o = 1; o < 32; o <<= 1) {
            int t = __shfl_up_sync(0xffffffffu, w, o);
            if (lane >= o) w += t;
        }
        wsum[lane] = w;
    }
    __syncthreads();
    int base = v - s + ((wid > 0) ? wsum[wid - 1] : 0);
    for (int i = st; i < en; i++) {
        g_off[i] = base;
        g_cur[i] = base;
        base += g_deg[i] + 1;
    }
    if (tid == 1023) g_off[n] = base;
}

// K4: CSR fill with in-order edge scalars + self loops.
__global__ void fill_kernel(const void* __restrict__ ei, int E, int Etot, int n) {
    int e = blockIdx.x * blockDim.x + threadIdx.x;
    if (e >= E + n) return;
    if (e < E) {
        int s = get_idx(ei, e);
        int d = get_idx(ei, E + e);
        if ((unsigned)d >= (unsigned)n || (unsigned)s >= (unsigned)n) return;
        int p = atomicAdd(&g_cur[d], 1);
        if (p < MAXET) {
            g_csrc[p] = s;
#pragma unroll
            for (int l = 0; l < 3; l++)
                g_cee[l * Etot + p] = g_ee[l * Etot + e];
        }
    } else {
        int i = e - E;
        int p = atomicAdd(&g_cur[i], 1);
        float invd = 1.f / fmaxf((float)g_deg[i], 1.f);
        if (p < MAXET) {
            g_csrc[p] = i;
#pragma unroll
            for (int l = 0; l < 3; l++)
                g_cee[l * Etot + p] = g_eesum[l * n + i] * invd;
        }
    }
}

// ---------------------------------------------------------------------------
// tf32 GEMM + fused scores. H[M,BN] = A[M,128]@W[128,BN]; ss=H@as, sd=H@ad.
// Block: 256 thr, 128 rows, full K in smem. Warp w: rows [w*16, w*16+16),
// all BN cols. Smem pad 132 -> bank=(4r+k)%32 conflict-free for frags.
template <int BN>
__global__ void __launch_bounds__(256, 1)
sgemm_tf32(const float* __restrict__ A, const float* __restrict__ B,
           const float* __restrict__ as_, const float* __restrict__ ad_,
           float* __restrict__ H, int M) {
    const int K = 128;
    const int NT = BN / 8;
    extern __shared__ unsigned smem_u[];
    unsigned* As = smem_u;                 // [128][132]
    unsigned* Bs = smem_u + 128 * 132;     // [BN][132] (transposed: [n][k])
    int tid = threadIdx.x;
    int lane = tid & 31, wid = tid >> 5;
    int row0 = blockIdx.x * 128;

    // Load A tile (128 x 128) coalesced, convert to tf32.
#pragma unroll
    for (int i = 0; i < 16; i++) {
        int f = tid + i * 256;            // float4 index in [0,4096)
        int r = f >> 5;
        int c4 = (f & 31) << 2;
        float4 v = make_float4(0.f, 0.f, 0.f, 0.f);
        int gr = row0 + r;
        if (gr < M) v = *(const float4*)(A + (size_t)gr * K + c4);
        unsigned* dst = &As[r * 132 + c4];
        dst[0] = f2tf32(v.x); dst[1] = f2tf32(v.y);
        dst[2] = f2tf32(v.z); dst[3] = f2tf32(v.w);
    }
    // Load W (128 x BN) -> Bs[n][k], convert to tf32.
#pragma unroll
    for (int i = 0; i < (K * BN) / 1024; i++) {
        int f4 = tid + i * 256;
        int f = f4 << 2;
        float4 v = *(const float4*)(B + f);
        int k = f / BN;
        int n = f % BN;
        Bs[(n + 0) * 132 + k] = f2tf32(v.x);
        Bs[(n + 1) * 132 + k] = f2tf32(v.y);
        Bs[(n + 2) * 132 + k] = f2tf32(v.z);
        Bs[(n + 3) * 132 + k] = f2tf32(v.w);
    }
    __syncthreads();

    int lr = lane >> 2, lc = lane & 3;
    float4 acc[NT];
#pragma unroll
    for (int nt = 0; nt < NT; nt++) acc[nt] = make_float4(0.f, 0.f, 0.f, 0.f);

    const unsigned* arow0 = &As[(wid * 16 + lr) * 132 + lc];
    const unsigned* arow8 = &As[(wid * 16 + lr + 8) * 132 + lc];
#pragma unroll 8
    for (int kk = 0; kk < K; kk += 4) {
        unsigned a0 = arow0[kk];
        unsigned a1 = arow8[kk];
#pragma unroll
        for (int nt = 0; nt < NT; nt++) {
            unsigned b0 = Bs[(nt * 8 + lr) * 132 + kk + lc];
            mma_tf32_k4(acc[nt], a0, a1, b0);
        }
    }

    // Epilogue: store H + fused scores.
    int growA = row0 + wid * 16 + lr;
    int growB = growA + 8;
    float s1A = 0.f, s2A = 0.f, s1B = 0.f, s2B = 0.f;
#pragma unroll
    for (int nt = 0; nt < NT; nt++) {
        int c0 = nt * 8 + 2 * lc;
        float4 c = acc[nt];
        float w1 = as_[c0], w1b = as_[c0 + 1];
        float w2 = ad_[c0], w2b = ad_[c0 + 1];
        s1A += c.x * w1 + c.y * w1b;
        s2A += c.x * w2 + c.y * w2b;
        s1B += c.z * w1 + c.w * w1b;
        s2B += c.z * w2 + c.w * w2b;
        if (growA < M) *(float2*)&H[(size_t)growA * BN + c0] = make_float2(c.x, c.y);
        if (growB < M) *(float2*)&H[(size_t)growB * BN + c0] = make_float2(c.z, c.w);
    }
    s1A += __shfl_xor_sync(0xffffffffu, s1A, 1);
    s1A += __shfl_xor_sync(0xffffffffu, s1A, 2);
    s2A += __shfl_xor_sync(0xffffffffu, s2A, 1);
    s2A += __shfl_xor_sync(0xffffffffu, s2A, 2);
    s1B += __shfl_xor_sync(0xffffffffu, s1B, 1);
    s1B += __shfl_xor_sync(0xffffffffu, s1B, 2);
    s2B += __shfl_xor_sync(0xffffffffu, s2B, 1);
    s2B += __shfl_xor_sync(0xffffffffu, s2B, 2);
    if (lc == 0) {
        if (growA < M) { g_ss[growA] = s1A; g_sd[growA] = s2A; }
        if (growB < M) { g_ss[growB] = s1B; g_sd[growB] = s2B; }
    }
}

// ---------------------------------------------------------------------------
// Warp-per-dst-node online softmax + aggregation, vectorized gather.
__global__ void aggregate128(int layer, int Etot, const float* __restrict__ bias,
                             float* __restrict__ out, int n) {
    const float* cee = g_cee + (size_t)layer * Etot;
    int node = blockIdx.x * (blockDim.x >> 5) + (threadIdx.x >> 5);
    int lane = threadIdx.x & 31;
    if (node >= n) return;
    int e0 = g_off[node], e1 = g_off[node + 1];
    float sdn = g_sd[node];

    float m = -INFINITY, denom = 0.f;
    float4 acc = make_float4(0.f, 0.f, 0.f, 0.f);

    for (int jb = e0; jb < e1; jb += 32) {
        int j = jb + lane;
        float a = -INFINITY;
        int s = 0;
        if (j < e1) {
            s = g_csrc[j];
            a = g_ss[s] + sdn + cee[j];
            a = (a > 0.f) ? a : 0.2f * a;
        }
        float bm = a;
#pragma unroll
        for (int o = 16; o; o >>= 1) bm = fmaxf(bm, __shfl_xor_sync(0xffffffffu, bm, o));
        float newm = fmaxf(m, bm);
        float scale = __expf(m - newm);
        denom *= scale;
        acc.x *= scale; acc.y *= scale; acc.z *= scale; acc.w *= scale;
        m = newm;
        float ex = (j < e1) ? __expf(a - m) : 0.f;
        denom += ex;
        int cnt = min(32, e1 - jb);
        for (int k = 0; k < cnt; k++) {
            float exk = __shfl_sync(0xffffffffu, ex, k);
            int sk = __shfl_sync(0xffffffffu, s, k);
            float4 hv = *(const float4*)(g_h + (size_t)sk * 128 + lane * 4);
            acc.x += exk * hv.x; acc.y += exk * hv.y;
            acc.z += exk * hv.z; acc.w += exk * hv.w;
        }
    }
#pragma unroll
    for (int o = 16; o; o >>= 1) denom += __shfl_xor_sync(0xffffffffu, denom, o);
    float inv = 1.f / (denom + 1e-16f);
    float4 b = *(const float4*)(bias + lane * 4);
    float4 r;
    r.x = fmaxf(acc.x * inv + b.x, 0.f);
    r.y = fmaxf(acc.y * inv + b.y, 0.f);
    r.z = fmaxf(acc.z * inv + b.z, 0.f);
    r.w = fmaxf(acc.w * inv + b.w, 0.f);
    *(float4*)(out + (size_t)node * 128 + lane * 4) = r;
}

__global__ void aggregate64(int layer, int Etot, const float* __restrict__ bias,
                            float* __restrict__ out, int n) {
    const float* cee = g_cee + (size_t)layer * Etot;
    int node = blockIdx.x * (blockDim.x >> 5) + (threadIdx.x >> 5);
    int lane = threadIdx.x & 31;
    if (node >= n) return;
    int e0 = g_off[node], e1 = g_off[node + 1];
    float sdn = g_sd[node];

    float m = -INFINITY, denom = 0.f;
    float2 acc = make_float2(0.f, 0.f);

    for (int jb = e0; jb < e1; jb += 32) {
        int j = jb + lane;
        float a = -INFINITY;
        int s = 0;
        if (j < e1) {
            s = g_csrc[j];
            a = g_ss[s] + sdn + cee[j];
            a = (a > 0.f) ? a : 0.2f * a;
        }
        float bm = a;
#pragma unroll
        for (int o = 16; o; o >>= 1) bm = fmaxf(bm, __shfl_xor_sync(0xffffffffu, bm, o));
        float newm = fmaxf(m, bm);
        float scale = __expf(m - newm);
        denom *= scale;
        acc.x *= scale; acc.y *= scale;
        m = newm;
        float ex = (j < e1) ? __expf(a - m) : 0.f;
        denom += ex;
        int cnt = min(32, e1 - jb);
        for (int k = 0; k < cnt; k++) {
            float exk = __shfl_sync(0xffffffffu, ex, k);
            int sk = __shfl_sync(0xffffffffu, s, k);
            float2 hv = *(const float2*)(g_h + (size_t)sk * 64 + lane * 2);
            acc.x += exk * hv.x; acc.y += exk * hv.y;
        }
    }
#pragma unroll
    for (int o = 16; o; o >>= 1) denom += __shfl_xor_sync(0xffffffffu, denom, o);
    float inv = 1.f / (denom + 1e-16f);
    float2 b = *(const float2*)(bias + lane * 2);
    float2 r;
    r.x = acc.x * inv + b.x;
    r.y = acc.y * inv + b.y;
    *(float2*)(out + (size_t)node * 64 + lane * 2) = r;
}

extern "C" void kernel_launch(void* const* d_in, const int* in_sizes, int n_in,
                              void* d_out, int out_size) {
    const float* x      = (const float*)d_in[0];
    const void*  ei     = d_in[1];
    const float* ea     = (const float*)d_in[2];
    const float* W[3]  = {(const float*)d_in[3],  (const float*)d_in[9],  (const float*)d_in[15]};
    const float* As_[3]= {(const float*)d_in[4],  (const float*)d_in[10], (const float*)d_in[16]};
    const float* Ad[3] = {(const float*)d_in[5],  (const float*)d_in[11], (const float*)d_in[17]};
    const float* We[3] = {(const float*)d_in[6],  (const float*)d_in[12], (const float*)d_in[18]};
    const float* Ae[3] = {(const float*)d_in[7],  (const float*)d_in[13], (const float*)d_in[19]};
    const float* Bb[3] = {(const float*)d_in[8],  (const float*)d_in[14], (const float*)d_in[20]};

    int N = in_sizes[0] / 128;
    int E = in_sizes[2] / 8;
    int Etot = E + N;
    int forced = (in_sizes[1] == 4 * E) ? 1 : -1;

    const int SMEM128 = (128 * 132 + 128 * 132) * 4;
    const int SMEM64  = (128 * 132 + 64 * 132) * 4;

    static float* h = nullptr;
    static float* bufA = nullptr;
    static float* bufB = nullptr;
    if (!h) {
        cudaGetSymbolAddress((void**)&h,    g_h);
        cudaGetSymbolAddress((void**)&bufA, g_bufA);
        cudaGetSymbolAddress((void**)&bufB, g_bufB);
        cudaFuncSetAttribute(sgemm_tf32<128>,
                             cudaFuncAttributeMaxDynamicSharedMemorySize, SMEM128);
        cudaFuncSetAttribute(sgemm_tf32<64>,
                             cudaFuncAttributeMaxDynamicSharedMemorySize, SMEM64);
    }

    int gb = (N + 127) / 128;
    int nb = (N + 7) / 8;

    // preprocessing (gemm0 interleaved at slot 4: depends only on x/W)
    init_kernel<<<(3 * N + 255) / 256, 256>>>((const int*)ei, forced,
                                              We[0], Ae[0], We[1], Ae[1], We[2], Ae[2], N);
    edge_kernel<<<(E + 255) / 256, 256>>>(ea, ei, E, Etot, N);
    scan_kernel<<<1, 1024>>>(N);
    sgemm_tf32<128><<<gb, 256, SMEM128>>>(x, W[0], As_[0], Ad[0], h, N);
    fill_kernel<<<(Etot + 255) / 256, 256>>>(ei, E, Etot, N);

    aggregate128<<<nb, 256>>>(0, Etot, Bb[0], bufA, N);
    sgemm_tf32<128><<<gb, 256, SMEM128>>>(bufA, W[1], As_[1], Ad[1], h, N);
    aggregate128<<<nb, 256>>>(1, Etot, Bb[1], bufB, N);
    sgemm_tf32<64><<<gb, 256, SMEM64>>>(bufB, W[2], As_[2], Ad[2], h, N);
    aggregate64<<<nb, 256>>>(2, Etot, Bb[2], (float*)d_out, N);
}

// round 6
// speedup vs baseline: 1.6219x; 1.0444x over previous
#include <cuda_runtime.h>
#include <cuda_bf16.h>
#include <math.h>

// ---------------------------------------------------------------------------
// GAT 3-layer pipeline. R6: tf32 mma.m16n8k8 GEMM, warp-tile 32x64, BK=64
// chunks for 2 CTAs/SM; aggregation gather unrolled x4.
// ---------------------------------------------------------------------------

#define MAXN 50048
#define MAXE 600064
#define MAXET (MAXE + MAXN)

__device__ float g_h[MAXN * 128];
__device__ float g_bufA[MAXN * 128];
__device__ float g_bufB[MAXN * 128];
__device__ float g_ss[MAXN];
__device__ float g_sd[MAXN];
__device__ float g_ee[3 * MAXET];
__device__ float g_cee[3 * MAXET];
__device__ float g_eesum[3 * MAXN];
__device__ int   g_deg[MAXN];
__device__ int   g_off[MAXN + 1];
__device__ int   g_cur[MAXN];
__device__ int   g_csrc[MAXET];
__device__ float g_v[24];
__device__ int   g_is64;

__device__ __forceinline__ int get_idx(const void* ei, int i) {
    if (g_is64) return (int)((const long long*)ei)[i];
    return ((const int*)ei)[i];
}

__device__ __forceinline__ unsigned f2tf32(float x) {
    unsigned u;
    asm("cvt.rna.tf32.f32 %0, %1;" : "=r"(u) : "f"(x));
    return u;
}

__device__ __forceinline__ void mma_k8(float4& c, const unsigned* a,
                                       unsigned b0, unsigned b1) {
    asm volatile(
        "mma.sync.aligned.m16n8k8.row.col.f32.tf32.tf32.f32 "
        "{%0,%1,%2,%3}, {%4,%5,%6,%7}, {%8,%9}, {%0,%1,%2,%3};"
        : "+f"(c.x), "+f"(c.y), "+f"(c.z), "+f"(c.w)
        : "r"(a[0]), "r"(a[1]), "r"(a[2]), "r"(a[3]), "r"(b0), "r"(b1));
}

// ---------------------------------------------------------------------------
__global__ void init_kernel(const int* __restrict__ eiw, int forced,
                            const float* We0, const float* ae0,
                            const float* We1, const float* ae1,
                            const float* We2, const float* ae2, int n) {
    int i = blockIdx.x * blockDim.x + threadIdx.x;
    int total = n * 3;
    for (int t = i; t < total; t += gridDim.x * blockDim.x) {
        g_eesum[t] = 0.f;
        if (t < n) g_deg[t] = 0;
    }
    if (blockIdx.x == 0) {
        if (threadIdx.x == 0) {
            if (forced >= 0) g_is64 = forced;
            else {
                int is64 = 1;
                for (int j = 1; j < 32; j += 2)
                    if (eiw[j] != 0) is64 = 0;
                g_is64 = is64;
            }
        }
        int t = (int)threadIdx.x - 32;
        if (t >= 0 && t < 24) {
            int l = t / 8, j = t % 8;
            const float* We = (l == 0) ? We0 : (l == 1) ? We1 : We2;
            const float* ae = (l == 0) ? ae0 : (l == 1) ? ae1 : ae2;
            int C = (l == 2) ? 64 : 128;
            float s = 0.f;
            for (int c = 0; c < C; c++) s += We[j * C + c] * ae[c];
            g_v[l * 8 + j] = s;
        }
    }
}

__global__ void edge_kernel(const float* __restrict__ ea,
                            const void* __restrict__ ei,
                            int E, int Etot, int n) {
    int e = blockIdx.x * blockDim.x + threadIdx.x;
    if (e >= E) return;
    float a[8];
#pragma unroll
    for (int j = 0; j < 8; j++) a[j] = ea[e * 8 + j];
    int d = get_idx(ei, E + e);
    bool ok = (unsigned)d < (unsigned)n;
    if (ok) atomicAdd(&g_deg[d], 1);
#pragma unroll
    for (int l = 0; l < 3; l++) {
        float s = 0.f;
#pragma unroll
        for (int j = 0; j < 8; j++) s += a[j] * g_v[l * 8 + j];
        g_ee[l * Etot + e] = s;
        if (ok) atomicAdd(&g_eesum[l * n + d], s);
    }
}

__global__ void scan_kernel(int n) {
    __shared__ int wsum[32];
    int tid = threadIdx.x;
    int per = (n + 1023) / 1024;
    int st = tid * per;
    int en = min(st + per, n);
    int s = 0;
    for (int i = st; i < en; i++) s += g_deg[i] + 1;
    int lane = tid & 31, wid = tid >> 5;
    int v = s;
#pragma unroll
    for (int o = 1; o < 32; o <<= 1) {
        int t = __shfl_up_sync(0xffffffffu, v, o);
        if (lane >= o) v += t;
    }
    if (lane == 31) wsum[wid] = v;
    __syncthreads();
    if (wid == 0) {
        int w = wsum[lane];
#pragma unroll
        for (int o = 1; o < 32; o <<= 1) {
            int t = __shfl_up_sync(0xffffffffu, w, o);
            if (lane >= o) w += t;
        }
        wsum[lane] = w;
    }
    __syncthreads();
    int base = v - s + ((wid > 0) ? wsum[wid - 1] : 0);
    for (int i = st; i < en; i++) {
        g_off[i] = base;
        g_cur[i] = base;
        base += g_deg[i] + 1;
    }
    if (tid == 1023) g_off[n] = base;
}

__global__ void fill_kernel(const void* __restrict__ ei, int E, int Etot, int n) {
    int e = blockIdx.x * blockDim.x + threadIdx.x;
    if (e >= E + n) return;
    if (e < E) {
        int s = get_idx(ei, e);
        int d = get_idx(ei, E + e);
        if ((unsigned)d >= (unsigned)n || (unsigned)s >= (unsigned)n) return;
        int p = atomicAdd(&g_cur[d], 1);
        if (p < MAXET) {
            g_csrc[p] = s;
#pragma unroll
            for (int l = 0; l < 3; l++)
                g_cee[l * Etot + p] = g_ee[l * Etot + e];
        }
    } else {
        int i = e - E;
        int p = atomicAdd(&g_cur[i], 1);
        float invd = 1.f / fmaxf((float)g_deg[i], 1.f);
        if (p < MAXET) {
            g_csrc[p] = i;
#pragma unroll
            for (int l = 0; l < 3; l++)
                g_cee[l * Etot + p] = g_eesum[l * n + i] * invd;
        }
    }
}

// ---------------------------------------------------------------------------
// tf32 GEMM (m16n8k8) + fused scores. H[M,BN]=A[M,128]@W[128,BN].
// 256 thr; BN=128: warp grid 4x2, warp tile 32x64. BN=64: 8x1, tile 16x64.
// BK=64 chunks; smem stride 68 -> bank=(4r+c)%32 conflict-free frag loads.
template <int BN>
__global__ void __launch_bounds__(256, 2)
sgemm_tf32(const float* __restrict__ A, const float* __restrict__ B,
           const float* __restrict__ as_, const float* __restrict__ ad_,
           float* __restrict__ H, int M) {
    const int K = 128, LDS_ = 68;
    const int MI = (BN == 128) ? 2 : 1;
    const int RPW = (BN == 128) ? 32 : 16;
    extern __shared__ unsigned smem_u[];
    unsigned* As = smem_u;                          // [128][68]
    unsigned* Bs = smem_u + 128 * LDS_;             // [BN][68]
    float* Sp = (float*)(smem_u + (128 + BN) * LDS_);  // [4][128] (BN==128)

    int tid = threadIdx.x;
    int lane = tid & 31, wid = tid >> 5;
    int g = lane >> 2, tq = lane & 3;
    int wr = (BN == 128) ? (wid & 3) : wid;
    int wc = (BN == 128) ? (wid >> 2) : 0;
    int row0 = blockIdx.x * 128;

    float4 acc[MI][8];
#pragma unroll
    for (int mi = 0; mi < MI; mi++)
#pragma unroll
        for (int nt = 0; nt < 8; nt++) acc[mi][nt] = make_float4(0.f, 0.f, 0.f, 0.f);

#pragma unroll
    for (int ch = 0; ch < 2; ch++) {
        int ko = ch * 64;
        if (ch) __syncthreads();
        // A chunk: 128 rows x 64 k.
#pragma unroll
        for (int i = 0; i < 8; i++) {
            int f = tid + i * 256;
            int r = f >> 4, c4 = (f & 15) << 2;
            float4 v = make_float4(0.f, 0.f, 0.f, 0.f);
            int gr = row0 + r;
            if (gr < M) v = *(const float4*)(A + (size_t)gr * K + ko + c4);
            unsigned* d = &As[r * LDS_ + c4];
            d[0] = f2tf32(v.x); d[1] = f2tf32(v.y);
            d[2] = f2tf32(v.z); d[3] = f2tf32(v.w);
        }
        // B chunk: 64 k x BN n -> Bs[n][k].
#pragma unroll
        for (int i = 0; i < BN / 16; i++) {
            int f = tid + i * 256;
            int k = f / (BN / 4);
            int n4 = (f % (BN / 4)) * 4;
            float4 v = *(const float4*)(B + (size_t)(ko + k) * BN + n4);
            Bs[(n4 + 0) * LDS_ + k] = f2tf32(v.x);
            Bs[(n4 + 1) * LDS_ + k] = f2tf32(v.y);
            Bs[(n4 + 2) * LDS_ + k] = f2tf32(v.z);
            Bs[(n4 + 3) * LDS_ + k] = f2tf32(v.w);
        }
        __syncthreads();
#pragma unroll
        for (int kk = 0; kk < 8; kk++) {
            int k0 = kk * 8;
            unsigned af[MI][4];
#pragma unroll
            for (int mi = 0; mi < MI; mi++) {
                int rb = wr * RPW + mi * 16;
                const unsigned* p0 = &As[(rb + g) * LDS_ + k0 + tq];
                const unsigned* p1 = &As[(rb + g + 8) * LDS_ + k0 + tq];
                af[mi][0] = p0[0]; af[mi][1] = p1[0];
                af[mi][2] = p0[4]; af[mi][3] = p1[4];
            }
#pragma unroll
            for (int nt = 0; nt < 8; nt++) {
                const unsigned* pb = &Bs[(wc * 64 + nt * 8 + g) * LDS_ + k0 + tq];
                unsigned b0 = pb[0], b1 = pb[4];
#pragma unroll
                for (int mi = 0; mi < MI; mi++)
                    mma_k8(acc[mi][nt], af[mi], b0, b1);
            }
        }
    }

    // Epilogue: H stores + fused attention scores.
    float s1l[MI], s2l[MI], s1h[MI], s2h[MI];
#pragma unroll
    for (int mi = 0; mi < MI; mi++) { s1l[mi]=s2l[mi]=s1h[mi]=s2h[mi]=0.f; }
#pragma unroll
    for (int mi = 0; mi < MI; mi++) {
        int rA = row0 + wr * RPW + mi * 16 + g;
#pragma unroll
        for (int nt = 0; nt < 8; nt++) {
            int c0 = wc * 64 + nt * 8 + 2 * tq;
            float w1 = as_[c0], w1b = as_[c0 + 1];
            float w2 = ad_[c0], w2b = ad_[c0 + 1];
            float4 c = acc[mi][nt];
            s1l[mi] += c.x * w1 + c.y * w1b;
            s2l[mi] += c.x * w2 + c.y * w2b;
            s1h[mi] += c.z * w1 + c.w * w1b;
            s2h[mi] += c.z * w2 + c.w * w2b;
            if (rA < M) *(float2*)&H[(size_t)rA * BN + c0] = make_float2(c.x, c.y);
            if (rA + 8 < M) *(float2*)&H[(size_t)(rA + 8) * BN + c0] = make_float2(c.z, c.w);
        }
    }
#pragma unroll
    for (int mi = 0; mi < MI; mi++) {
#pragma unroll
        for (int o = 1; o < 4; o <<= 1) {
            s1l[mi] += __shfl_xor_sync(0xffffffffu, s1l[mi], o);
            s2l[mi] += __shfl_xor_sync(0xffffffffu, s2l[mi], o);
            s1h[mi] += __shfl_xor_sync(0xffffffffu, s1h[mi], o);
            s2h[mi] += __shfl_xor_sync(0xffffffffu, s2h[mi], o);
        }
    }
    if (BN == 64) {
        if (tq == 0) {
            int rA = row0 + wr * RPW + g;
            if (rA < M)     { g_ss[rA] = s1l[0];     g_sd[rA] = s2l[0]; }
            if (rA + 8 < M) { g_ss[rA + 8] = s1h[0]; g_sd[rA + 8] = s2h[0]; }
        }
    } else {
        if (tq == 0) {
#pragma unroll
            for (int mi = 0; mi < MI; mi++) {
                int rib = wr * RPW + mi * 16 + g;
                Sp[wc * 128 + rib]       = s1l[mi];
                Sp[wc * 128 + rib + 8]   = s1h[mi];
                Sp[256 + wc * 128 + rib]     = s2l[mi];
                Sp[256 + wc * 128 + rib + 8] = s2h[mi];
            }
        }
        __syncthreads();
        if (tid < 128) {
            int r = row0 + tid;
            if (r < M) {
                g_ss[r] = Sp[tid] + Sp[128 + tid];
                g_sd[r] = Sp[256 + tid] + Sp[384 + tid];
            }
        }
    }
}

// ---------------------------------------------------------------------------
// Warp-per-dst-node online softmax + aggregation, 4x-unrolled gather.
__global__ void aggregate128(int layer, int Etot, const float* __restrict__ bias,
                             float* __restrict__ out, int n) {
    const float* cee = g_cee + (size_t)layer * Etot;
    int node = blockIdx.x * (blockDim.x >> 5) + (threadIdx.x >> 5);
    int lane = threadIdx.x & 31;
    if (node >= n) return;
    int e0 = g_off[node], e1 = g_off[node + 1];
    float sdn = g_sd[node];

    float m = -INFINITY, denom = 0.f;
    float4 acc = make_float4(0.f, 0.f, 0.f, 0.f);

    for (int jb = e0; jb < e1; jb += 32) {
        int j = jb + lane;
        float a = -INFINITY;
        int s = 0;
        if (j < e1) {
            s = g_csrc[j];
            a = g_ss[s] + sdn + cee[j];
            a = (a > 0.f) ? a : 0.2f * a;
        }
        float bm = a;
#pragma unroll
        for (int o = 16; o; o >>= 1) bm = fmaxf(bm, __shfl_xor_sync(0xffffffffu, bm, o));
        float newm = fmaxf(m, bm);
        float scale = __expf(m - newm);
        denom *= scale;
        acc.x *= scale; acc.y *= scale; acc.z *= scale; acc.w *= scale;
        m = newm;
        float ex = (j < e1) ? __expf(a - m) : 0.f;
        denom += ex;
        int cnt = min(32, e1 - jb);
        int k = 0;
        for (; k + 4 <= cnt; k += 4) {
            float e0f = __shfl_sync(0xffffffffu, ex, k);
            float e1f = __shfl_sync(0xffffffffu, ex, k + 1);
            float e2f = __shfl_sync(0xffffffffu, ex, k + 2);
            float e3f = __shfl_sync(0xffffffffu, ex, k + 3);
            int s0 = __shfl_sync(0xffffffffu, s, k);
            int s1 = __shfl_sync(0xffffffffu, s, k + 1);
            int s2 = __shfl_sync(0xffffffffu, s, k + 2);
            int s3 = __shfl_sync(0xffffffffu, s, k + 3);
            float4 h0 = *(const float4*)(g_h + (size_t)s0 * 128 + lane * 4);
            float4 h1 = *(const float4*)(g_h + (size_t)s1 * 128 + lane * 4);
            float4 h2 = *(const float4*)(g_h + (size_t)s2 * 128 + lane * 4);
            float4 h3 = *(const float4*)(g_h + (size_t)s3 * 128 + lane * 4);
            acc.x += e0f * h0.x + e1f * h1.x + e2f * h2.x + e3f * h3.x;
            acc.y += e0f * h0.y + e1f * h1.y + e2f * h2.y + e3f * h3.y;
            acc.z += e0f * h0.z + e1f * h1.z + e2f * h2.z + e3f * h3.z;
            acc.w += e0f * h0.w + e1f * h1.w + e2f * h2.w + e3f * h3.w;
        }
        for (; k < cnt; k++) {
            float exk = __shfl_sync(0xffffffffu, ex, k);
            int sk = __shfl_sync(0xffffffffu, s, k);
            float4 hv = *(const float4*)(g_h + (size_t)sk * 128 + lane * 4);
            acc.x += exk * hv.x; acc.y += exk * hv.y;
            acc.z += exk * hv.z; acc.w += exk * hv.w;
        }
    }
#pragma unroll
    for (int o = 16; o; o >>= 1) denom += __shfl_xor_sync(0xffffffffu, denom, o);
    float inv = 1.f / (denom + 1e-16f);
    float4 b = *(const float4*)(bias + lane * 4);
    float4 r;
    r.x = fmaxf(acc.x * inv + b.x, 0.f);
    r.y = fmaxf(acc.y * inv + b.y, 0.f);
    r.z = fmaxf(acc.z * inv + b.z, 0.f);
    r.w = fmaxf(acc.w * inv + b.w, 0.f);
    *(float4*)(out + (size_t)node * 128 + lane * 4) = r;
}

__global__ void aggregate64(int layer, int Etot, const float* __restrict__ bias,
                            float* __restrict__ out, int n) {
    const float* cee = g_cee + (size_t)layer * Etot;
    int node = blockIdx.x * (blockDim.x >> 5) + (threadIdx.x >> 5);
    int lane = threadIdx.x & 31;
    if (node >= n) return;
    int e0 = g_off[node], e1 = g_off[node + 1];
    float sdn = g_sd[node];

    float m = -INFINITY, denom = 0.f;
    float2 acc = make_float2(0.f, 0.f);

    for (int jb = e0; jb < e1; jb += 32) {
        int j = jb + lane;
        float a = -INFINITY;
        int s = 0;
        if (j < e1) {
            s = g_csrc[j];
            a = g_ss[s] + sdn + cee[j];
            a = (a > 0.f) ? a : 0.2f * a;
        }
        float bm = a;
#pragma unroll
        for (int o = 16; o; o >>= 1) bm = fmaxf(bm, __shfl_xor_sync(0xffffffffu, bm, o));
        float newm = fmaxf(m, bm);
        float scale = __expf(m - newm);
        denom *= scale;
        acc.x *= scale; acc.y *= scale;
        m = newm;
        float ex = (j < e1) ? __expf(a - m) : 0.f;
        denom += ex;
        int cnt = min(32, e1 - jb);
        int k = 0;
        for (; k + 4 <= cnt; k += 4) {
            float e0f = __shfl_sync(0xffffffffu, ex, k);
            float e1f = __shfl_sync(0xffffffffu, ex, k + 1);
            float e2f = __shfl_sync(0xffffffffu, ex, k + 2);
            float e3f = __shfl_sync(0xffffffffu, ex, k + 3);
            int s0 = __shfl_sync(0xffffffffu, s, k);
            int s1 = __shfl_sync(0xffffffffu, s, k + 1);
            int s2 = __shfl_sync(0xffffffffu, s, k + 2);
            int s3 = __shfl_sync(0xffffffffu, s, k + 3);
            float2 h0 = *(const float2*)(g_h + (size_t)s0 * 64 + lane * 2);
            float2 h1 = *(const float2*)(g_h + (size_t)s1 * 64 + lane * 2);
            float2 h2 = *(const float2*)(g_h + (size_t)s2 * 64 + lane * 2);
            float2 h3 = *(const float2*)(g_h + (size_t)s3 * 64 + lane * 2);
            acc.x += e0f * h0.x + e1f * h1.x + e2f * h2.x + e3f * h3.x;
            acc.y += e0f * h0.y + e1f * h1.y + e2f * h2.y + e3f * h3.y;
        }
        for (; k < cnt; k++) {
            float exk = __shfl_sync(0xffffffffu, ex, k);
            int sk = __shfl_sync(0xffffffffu, s, k);
            float2 hv = *(const float2*)(g_h + (size_t)sk * 64 + lane * 2);
            acc.x += exk * hv.x; acc.y += exk * hv.y;
        }
    }
#pragma unroll
    for (int o = 16; o; o >>= 1) denom += __shfl_xor_sync(0xffffffffu, denom, o);
    float inv = 1.f / (denom + 1e-16f);
    float2 b = *(const float2*)(bias + lane * 2);
    float2 r;
    r.x = acc.x * inv + b.x;
    r.y = acc.y * inv + b.y;
    *(float2*)(out + (size_t)node * 64 + lane * 2) = r;
}

extern "C" void kernel_launch(void* const* d_in, const int* in_sizes, int n_in,
                              void* d_out, int out_size) {
    const float* x      = (const float*)d_in[0];
    const void*  ei     = d_in[1];
    const float* ea     = (const float*)d_in[2];
    const float* W[3]  = {(const float*)d_in[3],  (const float*)d_in[9],  (const float*)d_in[15]};
    const float* As_[3]= {(const float*)d_in[4],  (const float*)d_in[10], (const float*)d_in[16]};
    const float* Ad[3] = {(const float*)d_in[5],  (const float*)d_in[11], (const float*)d_in[17]};
    const float* We[3] = {(const float*)d_in[6],  (const float*)d_in[12], (const float*)d_in[18]};
    const float* Ae[3] = {(const float*)d_in[7],  (const float*)d_in[13], (const float*)d_in[19]};
    const float* Bb[3] = {(const float*)d_in[8],  (const float*)d_in[14], (const float*)d_in[20]};

    int N = in_sizes[0] / 128;
    int E = in_sizes[2] / 8;
    int Etot = E + N;
    int forced = (in_sizes[1] == 4 * E) ? 1 : -1;

    const int SMEM128 = (128 + 128) * 68 * 4 + 512 * 4;   // 71680
    const int SMEM64  = (128 + 64) * 68 * 4;              // 52224

    static float* h = nullptr;
    static float* bufA = nullptr;
    static float* bufB = nullptr;
    if (!h) {
        cudaGetSymbolAddress((void**)&h,    g_h);
        cudaGetSymbolAddress((void**)&bufA, g_bufA);
        cudaGetSymbolAddress((void**)&bufB, g_bufB);
        cudaFuncSetAttribute(sgemm_tf32<128>,
                             cudaFuncAttributeMaxDynamicSharedMemorySize, SMEM128);
        cudaFuncSetAttribute(sgemm_tf32<64>,
                             cudaFuncAttributeMaxDynamicSharedMemorySize, SMEM64);
    }

    int gb = (N + 127) / 128;
    int nb = (N + 7) / 8;

    init_kernel<<<(3 * N + 255) / 256, 256>>>((const int*)ei, forced,
                                              We[0], Ae[0], We[1], Ae[1], We[2], Ae[2], N);
    edge_kernel<<<(E + 255) / 256, 256>>>(ea, ei, E, Etot, N);
    scan_kernel<<<1, 1024>>>(N);
    sgemm_tf32<128><<<gb, 256, SMEM128>>>(x, W[0], As_[0], Ad[0], h, N);
    fill_kernel<<<(Etot + 255) / 256, 256>>>(ei, E, Etot, N);

    aggregate128<<<nb, 256>>>(0, Etot, Bb[0], bufA, N);
    sgemm_tf32<128><<<gb, 256, SMEM128>>>(bufA, W[1], As_[1], Ad[1], h, N);
    aggregate128<<<nb, 256>>>(1, Etot, Bb[1], bufB, N);
    sgemm_tf32<64><<<gb, 256, SMEM64>>>(bufB, W[2], As_[2], Ad[2], h, N);
    aggregate64<<<nb, 256>>>(2, Etot, Bb[2], (float*)d_out, N);
}

// round 7
// speedup vs baseline: 1.6974x; 1.0466x over previous
#include <cuda_runtime.h>
#include <cuda_bf16.h>
#include <math.h>

// ---------------------------------------------------------------------------
// GAT 3-layer pipeline. R7: smem-free tf32 GEMM reading gmem fragment-layout
// operands (A-frag written by transform/aggregate kernels, W-frag by a tiny
// pre-kernel); aggregation gather unrolled x8.
// Frag layout (m16n8k8, validated R6): row r word = r*128 + kb*8 + tq*2 + j
// holds A[r][kb*8 + j*4 + tq] (tf32 bits). W-frag: word
// ((nb*16+kb)*32 + lane)*2 + j holds W[kb*8+j*4+(lane&3)][nb*8+(lane>>2)].
// ---------------------------------------------------------------------------

#define MAXN 50048
#define MAXE 600064
#define MAXET (MAXE + MAXN)

__device__ float    g_h[MAXN * 128];        // GEMM output (row-major, gathered)
__device__ unsigned g_xf[MAXN * 128];       // x in frag layout (tf32)
__device__ unsigned g_bufAf[MAXN * 128];    // layer-0 out, frag layout
__device__ unsigned g_bufBf[MAXN * 128];    // layer-1 out, frag layout
__device__ unsigned g_wf0[16384];
__device__ unsigned g_wf1[16384];
__device__ unsigned g_wf2[8192];
__device__ float    g_ss[MAXN];
__device__ float    g_sd[MAXN];
__device__ float    g_ee[3 * MAXET];
__device__ float    g_cee[3 * MAXET];
__device__ float    g_eesum[3 * MAXN];
__device__ int      g_deg[MAXN];
__device__ int      g_off[MAXN + 1];
__device__ int      g_cur[MAXN];
__device__ int      g_csrc[MAXET];
__device__ float    g_v[24];
__device__ int      g_is64;

__device__ __forceinline__ int get_idx(const void* ei, int i) {
    if (g_is64) return (int)((const long long*)ei)[i];
    return ((const int*)ei)[i];
}

__device__ __forceinline__ unsigned f2tf32(float x) {
    unsigned u;
    asm("cvt.rna.tf32.f32 %0, %1;" : "=r"(u) : "f"(x));
    return u;
}

__device__ __forceinline__ void mma_k8(float4& c, unsigned a0, unsigned a1,
                                       unsigned a2, unsigned a3,
                                       unsigned b0, unsigned b1) {
    asm volatile(
        "mma.sync.aligned.m16n8k8.row.col.f32.tf32.tf32.f32 "
        "{%0,%1,%2,%3}, {%4,%5,%6,%7}, {%8,%9}, {%0,%1,%2,%3};"
        : "+f"(c.x), "+f"(c.y), "+f"(c.z), "+f"(c.w)
        : "r"(a0), "r"(a1), "r"(a2), "r"(a3), "r"(b0), "r"(b1));
}

// ---------------------------------------------------------------------------
// T1: x (row-major fp32) -> frag layout tf32.
__global__ void xform_x(const float* __restrict__ X, int M) {
    int f = blockIdx.x * blockDim.x + threadIdx.x;
    if (f >= M * 32) return;
    int r = f >> 5, c4 = (f & 31) << 2;
    float4 v = *(const float4*)(X + (size_t)r * 128 + c4);
    int kb = c4 >> 3, j = (c4 >> 2) & 1;
    unsigned* base = g_xf + (size_t)r * 128 + kb * 8 + j;
    base[0] = f2tf32(v.x); base[2] = f2tf32(v.y);
    base[4] = f2tf32(v.z); base[6] = f2tf32(v.w);
}

// T2: W0/W1/W2 (row-major [K][BN]) -> frag layout tf32.
__global__ void xform_w(const float* __restrict__ W0, const float* __restrict__ W1,
                        const float* __restrict__ W2) {
    int idx = blockIdx.x * blockDim.x + threadIdx.x;  // 0 .. 40960
    int l, e;
    if (idx < 16384)       { l = 0; e = idx; }
    else if (idx < 32768)  { l = 1; e = idx - 16384; }
    else if (idx < 40960)  { l = 2; e = idx - 32768; }
    else return;
    int BN = (l == 2) ? 64 : 128;
    int k = e / BN, n = e % BN;
    const float* W = (l == 0) ? W0 : (l == 1) ? W1 : W2;
    unsigned* Wf = (l == 0) ? g_wf0 : (l == 1) ? g_wf1 : g_wf2;
    int lane = (n & 7) * 4 + (k & 3);
    int j = (k >> 2) & 1;
    int word = (((n >> 3) * 16 + (k >> 3)) * 32 + lane) * 2 + j;
    Wf[word] = f2tf32(W[k * BN + n]);
}

// ---------------------------------------------------------------------------
__global__ void init_kernel(const int* __restrict__ eiw, int forced,
                            const float* We0, const float* ae0,
                            const float* We1, const float* ae1,
                            const float* We2, const float* ae2, int n) {
    int i = blockIdx.x * blockDim.x + threadIdx.x;
    int total = n * 3;
    for (int t = i; t < total; t += gridDim.x * blockDim.x) {
        g_eesum[t] = 0.f;
        if (t < n) g_deg[t] = 0;
    }
    if (blockIdx.x == 0) {
        if (threadIdx.x == 0) {
            if (forced >= 0) g_is64 = forced;
            else {
                int is64 = 1;
                for (int j = 1; j < 32; j += 2)
                    if (eiw[j] != 0) is64 = 0;
                g_is64 = is64;
            }
        }
        int t = (int)threadIdx.x - 32;
        if (t >= 0 && t < 24) {
            int l = t / 8, j = t % 8;
            const float* We = (l == 0) ? We0 : (l == 1) ? We1 : We2;
            const float* ae = (l == 0) ? ae0 : (l == 1) ? ae1 : ae2;
            int C = (l == 2) ? 64 : 128;
            float s = 0.f;
            for (int c = 0; c < C; c++) s += We[j * C + c] * ae[c];
            g_v[l * 8 + j] = s;
        }
    }
}

__global__ void edge_kernel(const float* __restrict__ ea,
                            const void* __restrict__ ei,
                            int E, int Etot, int n) {
    int e = blockIdx.x * blockDim.x + threadIdx.x;
    if (e >= E) return;
    float a[8];
#pragma unroll
    for (int j = 0; j < 8; j++) a[j] = ea[e * 8 + j];
    int d = get_idx(ei, E + e);
    bool ok = (unsigned)d < (unsigned)n;
    if (ok) atomicAdd(&g_deg[d], 1);
#pragma unroll
    for (int l = 0; l < 3; l++) {
        float s = 0.f;
#pragma unroll
        for (int j = 0; j < 8; j++) s += a[j] * g_v[l * 8 + j];
        g_ee[l * Etot + e] = s;
        if (ok) atomicAdd(&g_eesum[l * n + d], s);
    }
}

__global__ void scan_kernel(int n) {
    __shared__ int wsum[32];
    int tid = threadIdx.x;
    int per = (n + 1023) / 1024;
    int st = tid * per;
    int en = min(st + per, n);
    int s = 0;
    for (int i = st; i < en; i++) s += g_deg[i] + 1;
    int lane = tid & 31, wid = tid >> 5;
    int v = s;
#pragma unroll
    for (int o = 1; o < 32; o <<= 1) {
        int t = __shfl_up_sync(0xffffffffu, v, o);
        if (lane >= o) v += t;
    }
    if (lane == 31) wsum[wid] = v;
    __syncthreads();
    if (wid == 0) {
        int w = wsum[lane];
#pragma unroll
        for (int o = 1; o < 32; o <<= 1) {
            int t = __shfl_up_sync(0xffffffffu, w, o);
            if (lane >= o) w += t;
        }
        wsum[lane] = w;
    }
    __syncthreads();
    int base = v - s + ((wid > 0) ? wsum[wid - 1] : 0);
    for (int i = st; i < en; i++) {
        g_off[i] = base;
        g_cur[i] = base;
        base += g_deg[i] + 1;
    }
    if (tid == 1023) g_off[n] = base;
}

__global__ void fill_kernel(const void* __restrict__ ei, int E, int Etot, int n) {
    int e = blockIdx.x * blockDim.x + threadIdx.x;
    if (e >= E + n) return;
    if (e < E) {
        int s = get_idx(ei, e);
        int d = get_idx(ei, E + e);
        if ((unsigned)d >= (unsigned)n || (unsigned)s >= (unsigned)n) return;
        int p = atomicAdd(&g_cur[d], 1);
        if (p < MAXET) {
            g_csrc[p] = s;
#pragma unroll
            for (int l = 0; l < 3; l++)
                g_cee[l * Etot + p] = g_ee[l * Etot + e];
        }
    } else {
        int i = e - E;
        int p = atomicAdd(&g_cur[i], 1);
        float invd = 1.f / fmaxf((float)g_deg[i], 1.f);
        if (p < MAXET) {
            g_csrc[p] = i;
#pragma unroll
            for (int l = 0; l < 3; l++)
                g_cee[l * Etot + p] = g_eesum[l * n + i] * invd;
        }
    }
}

// ---------------------------------------------------------------------------
// Smem-free tf32 GEMM + fused scores. H[M,BN] = A@W from frag-layout gmem.
// 256 thr; BN=128: warps 4x2 (wr,wc), warp tile 32x64, MI=2. BN=64: 8x1, MI=1.
template <int BN>
__global__ void __launch_bounds__(256, 2)
gemm_frag(const unsigned* __restrict__ Af, const unsigned* __restrict__ Wf,
          const float* __restrict__ as_, const float* __restrict__ ad_,
          float* __restrict__ H, int M) {
    const int MI = (BN == 128) ? 2 : 1;
    const int RPW = (BN == 128) ? 32 : 16;
    __shared__ float Sp[512];
    int tid = threadIdx.x;
    int lane = tid & 31, wid = tid >> 5;
    int g = lane >> 2, tq = lane & 3;
    int wr = (BN == 128) ? (wid & 3) : wid;
    int wc = (BN == 128) ? (wid >> 2) : 0;
    int row0 = blockIdx.x * 128;

    float4 acc[MI][8];
#pragma unroll
    for (int mi = 0; mi < MI; mi++)
#pragma unroll
        for (int nt = 0; nt < 8; nt++) acc[mi][nt] = make_float4(0.f, 0.f, 0.f, 0.f);

    const unsigned* pa[MI][2];
#pragma unroll
    for (int mi = 0; mi < MI; mi++) {
        int rb = row0 + wr * RPW + mi * 16;
        pa[mi][0] = Af + (size_t)(rb + g) * 128 + tq * 2;
        pa[mi][1] = Af + (size_t)(rb + g + 8) * 128 + tq * 2;
    }
    const unsigned* pb = Wf + ((size_t)(wc * 8) * 16 * 32 + lane) * 2;

#pragma unroll
    for (int kb = 0; kb < 16; kb++) {
        uint2 au[MI], av[MI];
#pragma unroll
        for (int mi = 0; mi < MI; mi++) {
            au[mi] = *(const uint2*)(pa[mi][0] + kb * 8);
            av[mi] = *(const uint2*)(pa[mi][1] + kb * 8);
        }
#pragma unroll
        for (int nt = 0; nt < 8; nt++) {
            uint2 b = *(const uint2*)(pb + (nt * 16 + kb) * 64);
#pragma unroll
            for (int mi = 0; mi < MI; mi++)
                mma_k8(acc[mi][nt], au[mi].x, av[mi].x, au[mi].y, av[mi].y,
                       b.x, b.y);
        }
    }

    // Epilogue: H stores + fused attention scores.
    float s1l[MI], s2l[MI], s1h[MI], s2h[MI];
#pragma unroll
    for (int mi = 0; mi < MI; mi++) { s1l[mi]=s2l[mi]=s1h[mi]=s2h[mi]=0.f; }
#pragma unroll
    for (int mi = 0; mi < MI; mi++) {
        int rA = row0 + wr * RPW + mi * 16 + g;
#pragma unroll
        for (int nt = 0; nt < 8; nt++) {
            int c0 = wc * 64 + nt * 8 + 2 * tq;
            float w1 = as_[c0], w1b = as_[c0 + 1];
            float w2 = ad_[c0], w2b = ad_[c0 + 1];
            float4 c = acc[mi][nt];
            s1l[mi] += c.x * w1 + c.y * w1b;
            s2l[mi] += c.x * w2 + c.y * w2b;
            s1h[mi] += c.z * w1 + c.w * w1b;
            s2h[mi] += c.z * w2 + c.w * w2b;
            if (rA < M) *(float2*)&H[(size_t)rA * BN + c0] = make_float2(c.x, c.y);
            if (rA + 8 < M) *(float2*)&H[(size_t)(rA + 8) * BN + c0] = make_float2(c.z, c.w);
        }
    }
#pragma unroll
    for (int mi = 0; mi < MI; mi++) {
#pragma unroll
        for (int o = 1; o < 4; o <<= 1) {
            s1l[mi] += __shfl_xor_sync(0xffffffffu, s1l[mi], o);
            s2l[mi] += __shfl_xor_sync(0xffffffffu, s2l[mi], o);
            s1h[mi] += __shfl_xor_sync(0xffffffffu, s1h[mi], o);
            s2h[mi] += __shfl_xor_sync(0xffffffffu, s2h[mi], o);
        }
    }
    if (BN == 64) {
        if (tq == 0) {
            int rA = row0 + wr * RPW + g;
            if (rA < M)     { g_ss[rA] = s1l[0];     g_sd[rA] = s2l[0]; }
            if (rA + 8 < M) { g_ss[rA + 8] = s1h[0]; g_sd[rA + 8] = s2h[0]; }
        }
    } else {
        if (tq == 0) {
#pragma unroll
            for (int mi = 0; mi < MI; mi++) {
                int rib = wr * RPW + mi * 16 + g;
                Sp[wc * 128 + rib]           = s1l[mi];
                Sp[wc * 128 + rib + 8]       = s1h[mi];
                Sp[256 + wc * 128 + rib]     = s2l[mi];
                Sp[256 + wc * 128 + rib + 8] = s2h[mi];
            }
        }
        __syncthreads();
        if (tid < 128) {
            int r = row0 + tid;
            if (r < M) {
                g_ss[r] = Sp[tid] + Sp[128 + tid];
                g_sd[r] = Sp[256 + tid] + Sp[384 + tid];
            }
        }
    }
}

// ---------------------------------------------------------------------------
// Warp-per-dst-node online softmax + aggregation (C=128), 8x-unrolled gather,
// writes output in FRAG layout (tf32) for the next GEMM.
__global__ void aggregate128(int layer, int Etot, const float* __restrict__ bias,
                             unsigned* __restrict__ outf, int n) {
    const float* cee = g_cee + (size_t)layer * Etot;
    int node = blockIdx.x * (blockDim.x >> 5) + (threadIdx.x >> 5);
    int lane = threadIdx.x & 31;
    if (node >= n) return;
    int e0 = g_off[node], e1 = g_off[node + 1];
    float sdn = g_sd[node];

    float m = -INFINITY, denom = 0.f;
    float4 acc = make_float4(0.f, 0.f, 0.f, 0.f);

    for (int jb = e0; jb < e1; jb += 32) {
        int j = jb + lane;
        float a = -INFINITY;
        int s = 0;
        if (j < e1) {
            s = g_csrc[j];
            a = g_ss[s] + sdn + cee[j];
            a = (a > 0.f) ? a : 0.2f * a;
        }
        float bm = a;
#pragma unroll
        for (int o = 16; o; o >>= 1) bm = fmaxf(bm, __shfl_xor_sync(0xffffffffu, bm, o));
        float newm = fmaxf(m, bm);
        float scale = __expf(m - newm);
        denom *= scale;
        acc.x *= scale; acc.y *= scale; acc.z *= scale; acc.w *= scale;
        m = newm;
        float ex = (j < e1) ? __expf(a - m) : 0.f;
        denom += ex;
        int cnt = min(32, e1 - jb);
        int k = 0;
        for (; k + 8 <= cnt; k += 8) {
            float ef[8]; int sv[8];
#pragma unroll
            for (int q = 0; q < 8; q++) {
                ef[q] = __shfl_sync(0xffffffffu, ex, k + q);
                sv[q] = __shfl_sync(0xffffffffu, s, k + q);
            }
            float4 hv[8];
#pragma unroll
            for (int q = 0; q < 8; q++)
                hv[q] = *(const float4*)(g_h + (size_t)sv[q] * 128 + lane * 4);
#pragma unroll
            for (int q = 0; q < 8; q++) {
                acc.x += ef[q] * hv[q].x; acc.y += ef[q] * hv[q].y;
                acc.z += ef[q] * hv[q].z; acc.w += ef[q] * hv[q].w;
            }
        }
        for (; k < cnt; k++) {
            float exk = __shfl_sync(0xffffffffu, ex, k);
            int sk = __shfl_sync(0xffffffffu, s, k);
            float4 hv = *(const float4*)(g_h + (size_t)sk * 128 + lane * 4);
            acc.x += exk * hv.x; acc.y += exk * hv.y;
            acc.z += exk * hv.z; acc.w += exk * hv.w;
        }
    }
#pragma unroll
    for (int o = 16; o; o >>= 1) denom += __shfl_xor_sync(0xffffffffu, denom, o);
    float inv = 1.f / (denom + 1e-16f);
    float4 b = *(const float4*)(bias + lane * 4);
    float4 r;
    r.x = fmaxf(acc.x * inv + b.x, 0.f);
    r.y = fmaxf(acc.y * inv + b.y, 0.f);
    r.z = fmaxf(acc.z * inv + b.z, 0.f);
    r.w = fmaxf(acc.w * inv + b.w, 0.f);
    // frag-layout store: k = lane*4 + t -> word = node*128 + (lane>>1)*8 + t*2 + (lane&1)
    unsigned* base = outf + (size_t)node * 128 + (lane >> 1) * 8 + (lane & 1);
    base[0] = f2tf32(r.x); base[2] = f2tf32(r.y);
    base[4] = f2tf32(r.z); base[6] = f2tf32(r.w);
}

// Final layer (C=64): row-major fp32 output, no relu.
__global__ void aggregate64(int layer, int Etot, const float* __restrict__ bias,
                            float* __restrict__ out, int n) {
    const float* cee = g_cee + (size_t)layer * Etot;
    int node = blockIdx.x * (blockDim.x >> 5) + (threadIdx.x >> 5);
    int lane = threadIdx.x & 31;
    if (node >= n) return;
    int e0 = g_off[node], e1 = g_off[node + 1];
    float sdn = g_sd[node];

    float m = -INFINITY, denom = 0.f;
    float2 acc = make_float2(0.f, 0.f);

    for (int jb = e0; jb < e1; jb += 32) {
        int j = jb + lane;
        float a = -INFINITY;
        int s = 0;
        if (j < e1) {
            s = g_csrc[j];
            a = g_ss[s] + sdn + cee[j];
            a = (a > 0.f) ? a : 0.2f * a;
        }
        float bm = a;
#pragma unroll
        for (int o = 16; o; o >>= 1) bm = fmaxf(bm, __shfl_xor_sync(0xffffffffu, bm, o));
        float newm = fmaxf(m, bm);
        float scale = __expf(m - newm);
        denom *= scale;
        acc.x *= scale; acc.y *= scale;
        m = newm;
        float ex = (j < e1) ? __expf(a - m) : 0.f;
        denom += ex;
        int cnt = min(32, e1 - jb);
        int k = 0;
        for (; k + 8 <= cnt; k += 8) {
            float ef[8]; int sv[8];
#pragma unroll
            for (int q = 0; q < 8; q++) {
                ef[q] = __shfl_sync(0xffffffffu, ex, k + q);
                sv[q] = __shfl_sync(0xffffffffu, s, k + q);
            }
            float2 hv[8];
#pragma unroll
            for (int q = 0; q < 8; q++)
                hv[q] = *(const float2*)(g_h + (size_t)sv[q] * 64 + lane * 2);
#pragma unroll
            for (int q = 0; q < 8; q++) {
                acc.x += ef[q] * hv[q].x; acc.y += ef[q] * hv[q].y;
            }
        }
        for (; k < cnt; k++) {
            float exk = __shfl_sync(0xffffffffu, ex, k);
            int sk = __shfl_sync(0xffffffffu, s, k);
            float2 hv = *(const float2*)(g_h + (size_t)sk * 64 + lane * 2);
            acc.x += exk * hv.x; acc.y += exk * hv.y;
        }
    }
#pragma unroll
    for (int o = 16; o; o >>= 1) denom += __shfl_xor_sync(0xffffffffu, denom, o);
    float inv = 1.f / (denom + 1e-16f);
    float2 b = *(const float2*)(bias + lane * 2);
    float2 r;
    r.x = acc.x * inv + b.x;
    r.y = acc.y * inv + b.y;
    *(float2*)(out + (size_t)node * 64 + lane * 2) = r;
}

extern "C" void kernel_launch(void* const* d_in, const int* in_sizes, int n_in,
                              void* d_out, int out_size) {
    const float* x      = (const float*)d_in[0];
    const void*  ei     = d_in[1];
    const float* ea     = (const float*)d_in[2];
    const float* W[3]  = {(const float*)d_in[3],  (const float*)d_in[9],  (const float*)d_in[15]};
    const float* As_[3]= {(const float*)d_in[4],  (const float*)d_in[10], (const float*)d_in[16]};
    const float* Ad[3] = {(const float*)d_in[5],  (const float*)d_in[11], (const float*)d_in[17]};
    const float* We[3] = {(const float*)d_in[6],  (const float*)d_in[12], (const float*)d_in[18]};
    const float* Ae[3] = {(const float*)d_in[7],  (const float*)d_in[13], (const float*)d_in[19]};
    const float* Bb[3] = {(const float*)d_in[8],  (const float*)d_in[14], (const float*)d_in[20]};

    int N = in_sizes[0] / 128;
    int E = in_sizes[2] / 8;
    int Etot = E + N;
    int forced = (in_sizes[1] == 4 * E) ? 1 : -1;

    static float* h = nullptr;
    static unsigned *xf = nullptr, *bufAf = nullptr, *bufBf = nullptr;
    static unsigned *wf0 = nullptr, *wf1 = nullptr, *wf2 = nullptr;
    if (!h) {
        cudaGetSymbolAddress((void**)&h,     g_h);
        cudaGetSymbolAddress((void**)&xf,    g_xf);
        cudaGetSymbolAddress((void**)&bufAf, g_bufAf);
        cudaGetSymbolAddress((void**)&bufBf, g_bufBf);
        cudaGetSymbolAddress((void**)&wf0,   g_wf0);
        cudaGetSymbolAddress((void**)&wf1,   g_wf1);
        cudaGetSymbolAddress((void**)&wf2,   g_wf2);
    }

    int gb = (N + 127) / 128;
    int nb = (N + 7) / 8;

    // 1-2: operand transforms
    xform_x<<<(N * 32 + 255) / 256, 256>>>(x, N);
    xform_w<<<(40960 + 255) / 256, 256>>>(W[0], W[1], W[2]);
    // 3: init; 4: gemm0 (profiled slot)
    init_kernel<<<(3 * N + 255) / 256, 256>>>((const int*)ei, forced,
                                              We[0], Ae[0], We[1], Ae[1], We[2], Ae[2], N);
    gemm_frag<128><<<gb, 256>>>(xf, wf0, As_[0], Ad[0], h, N);
    // 5-7: graph preprocessing
    edge_kernel<<<(E + 255) / 256, 256>>>(ea, ei, E, Etot, N);
    scan_kernel<<<1, 1024>>>(N);
    fill_kernel<<<(Etot + 255) / 256, 256>>>(ei, E, Etot, N);
    // 8-12: layers
    aggregate128<<<nb, 256>>>(0, Etot, Bb[0], bufAf, N);
    gemm_frag<128><<<gb, 256>>>(bufAf, wf1, As_[1], Ad[1], h, N);
    aggregate128<<<nb, 256>>>(1, Etot, Bb[1], bufBf, N);
    gemm_frag<64><<<gb, 256>>>(bufBf, wf2, As_[2], Ad[2], h, N);
    aggregate64<<<nb, 256>>>(2, Etot, Bb[2], (float*)d_out, N);
}

// round 8
// speedup vs baseline: 1.8147x; 1.0691x over previous
#include <cuda_runtime.h>
#include <cuda_fp16.h>
#include <math.h>

// ---------------------------------------------------------------------------
// GAT 3-layer pipeline. R8: h stored fp16 (halves gather traffic), fused
// edge->CSR preprocessing (no ee intermediate, no eesum atomics; self-loop
// occupies first CSR slot, mean computed from own cee range).
// ---------------------------------------------------------------------------

#define MAXN 50048
#define MAXE 600064
#define MAXET (MAXE + MAXN)

__device__ __half   g_h[MAXN * 128];        // GEMM output (row-major fp16)
__device__ unsigned g_xf[MAXN * 128];       // x in frag layout (tf32)
__device__ unsigned g_bufAf[MAXN * 128];    // layer-0 out, frag layout
__device__ unsigned g_bufBf[MAXN * 128];    // layer-1 out, frag layout
__device__ unsigned g_wf0[16384];
__device__ unsigned g_wf1[16384];
__device__ unsigned g_wf2[8192];
__device__ float    g_ss[MAXN];
__device__ float    g_sd[MAXN];
__device__ float    g_cee[3 * MAXET];       // per-slot scalar, CSR order
__device__ int      g_deg[MAXN];
__device__ int      g_off[MAXN + 1];
__device__ int      g_cur[MAXN];
__device__ int      g_csrc[MAXET];
__device__ float    g_v[24];
__device__ int      g_is64;

__device__ __forceinline__ int get_idx(const void* ei, int i) {
    if (g_is64) return (int)((const long long*)ei)[i];
    return ((const int*)ei)[i];
}

__device__ __forceinline__ unsigned f2tf32(float x) {
    unsigned u;
    asm("cvt.rna.tf32.f32 %0, %1;" : "=r"(u) : "f"(x));
    return u;
}

__device__ __forceinline__ void mma_k8(float4& c, unsigned a0, unsigned a1,
                                       unsigned a2, unsigned a3,
                                       unsigned b0, unsigned b1) {
    asm volatile(
        "mma.sync.aligned.m16n8k8.row.col.f32.tf32.tf32.f32 "
        "{%0,%1,%2,%3}, {%4,%5,%6,%7}, {%8,%9}, {%0,%1,%2,%3};"
        : "+f"(c.x), "+f"(c.y), "+f"(c.z), "+f"(c.w)
        : "r"(a0), "r"(a1), "r"(a2), "r"(a3), "r"(b0), "r"(b1));
}

// ---------------------------------------------------------------------------
// K1: x -> frag layout, W0/W1/W2 -> frag layout (fused).
__global__ void xform_kernel(const float* __restrict__ X,
                             const float* __restrict__ W0,
                             const float* __restrict__ W1,
                             const float* __restrict__ W2, int M) {
    int f = blockIdx.x * blockDim.x + threadIdx.x;
    if (f < M * 32) {
        int r = f >> 5, c4 = (f & 31) << 2;
        float4 v = *(const float4*)(X + (size_t)r * 128 + c4);
        int kb = c4 >> 3, j = (c4 >> 2) & 1;
        unsigned* base = g_xf + (size_t)r * 128 + kb * 8 + j;
        base[0] = f2tf32(v.x); base[2] = f2tf32(v.y);
        base[4] = f2tf32(v.z); base[6] = f2tf32(v.w);
        return;
    }
    int idx = f - M * 32;
    int l, e;
    if (idx < 16384)       { l = 0; e = idx; }
    else if (idx < 32768)  { l = 1; e = idx - 16384; }
    else if (idx < 40960)  { l = 2; e = idx - 32768; }
    else return;
    int BN = (l == 2) ? 64 : 128;
    int k = e / BN, n = e % BN;
    const float* W = (l == 0) ? W0 : (l == 1) ? W1 : W2;
    unsigned* Wf = (l == 0) ? g_wf0 : (l == 1) ? g_wf1 : g_wf2;
    int lane = (n & 7) * 4 + (k & 3);
    int j = (k >> 2) & 1;
    int word = (((n >> 3) * 16 + (k >> 3)) * 32 + lane) * 2 + j;
    Wf[word] = f2tf32(W[k * BN + n]);
}

// K2: zero deg + detect is64 + compute v = We^T @ ae per layer.
__global__ void init_kernel(const int* __restrict__ eiw, int forced,
                            const float* We0, const float* ae0,
                            const float* We1, const float* ae1,
                            const float* We2, const float* ae2, int n) {
    int i = blockIdx.x * blockDim.x + threadIdx.x;
    for (int t = i; t < n; t += gridDim.x * blockDim.x) g_deg[t] = 0;
    if (blockIdx.x == 0) {
        if (threadIdx.x == 0) {
            if (forced >= 0) g_is64 = forced;
            else {
                int is64 = 1;
                for (int j = 1; j < 32; j += 2)
                    if (eiw[j] != 0) is64 = 0;
                g_is64 = is64;
            }
        }
        int t = (int)threadIdx.x - 32;
        if (t >= 0 && t < 24) {
            int l = t / 8, j = t % 8;
            const float* We = (l == 0) ? We0 : (l == 1) ? We1 : We2;
            const float* ae = (l == 0) ? ae0 : (l == 1) ? ae1 : ae2;
            int C = (l == 2) ? 64 : 128;
            float s = 0.f;
            for (int c = 0; c < C; c++) s += We[j * C + c] * ae[c];
            g_v[l * 8 + j] = s;
        }
    }
}

// K3: degree count.
__global__ void count_kernel(const void* __restrict__ ei, int E, int n) {
    int e = blockIdx.x * blockDim.x + threadIdx.x;
    if (e >= E) return;
    int d = get_idx(ei, E + e);
    if ((unsigned)d < (unsigned)n) atomicAdd(&g_deg[d], 1);
}

// K5: single-block scan of (deg+1); cur starts past the self-loop slot.
__global__ void scan_kernel(int n) {
    __shared__ int wsum[32];
    int tid = threadIdx.x;
    int per = (n + 1023) / 1024;
    int st = tid * per;
    int en = min(st + per, n);
    int s = 0;
    for (int i = st; i < en; i++) s += g_deg[i] + 1;
    int lane = tid & 31, wid = tid >> 5;
    int v = s;
#pragma unroll
    for (int o = 1; o < 32; o <<= 1) {
        int t = __shfl_up_sync(0xffffffffu, v, o);
        if (lane >= o) v += t;
    }
    if (lane == 31) wsum[wid] = v;
    __syncthreads();
    if (wid == 0) {
        int w = wsum[lane];
#pragma unroll
        for (int o = 1; o < 32; o <<= 1) {
            int t = __shfl_up_sync(0xffffffffu, w, o);
            if (lane >= o) w += t;
        }
        wsum[lane] = w;
    }
    __syncthreads();
    int base = v - s + ((wid > 0) ? wsum[wid - 1] : 0);
    for (int i = st; i < en; i++) {
        g_off[i] = base;
        g_cur[i] = base + 1;          // slot 0 reserved for self loop
        base += g_deg[i] + 1;
    }
    if (tid == 1023) g_off[n] = base;
}

// K6: fused edge scalar + CSR scatter (no intermediate, no eesum atomics).
__global__ void edgefill_kernel(const float* __restrict__ ea,
                                const void* __restrict__ ei,
                                int E, int Etot, int n) {
    int e = blockIdx.x * blockDim.x + threadIdx.x;
    if (e >= E) return;
    int s = get_idx(ei, e);
    int d = get_idx(ei, E + e);
    if ((unsigned)d >= (unsigned)n || (unsigned)s >= (unsigned)n) return;
    float a[8];
#pragma unroll
    for (int j = 0; j < 8; j++) a[j] = ea[e * 8 + j];
    int p = atomicAdd(&g_cur[d], 1);
    if (p >= MAXET) return;
    g_csrc[p] = s;
#pragma unroll
    for (int l = 0; l < 3; l++) {
        float sv = 0.f;
#pragma unroll
        for (int j = 0; j < 8; j++) sv += a[j] * g_v[l * 8 + j];
        g_cee[l * Etot + p] = sv;
    }
}

// K7: self-loop slot: warp per node sums its own cee range -> mean.
__global__ void selfloop_kernel(int Etot, int n) {
    int node = blockIdx.x * (blockDim.x >> 5) + (threadIdx.x >> 5);
    int lane = threadIdx.x & 31;
    if (node >= n) return;
    int e0 = g_off[node], e1 = g_off[node + 1];
    float s0 = 0.f, s1 = 0.f, s2 = 0.f;
    for (int j = e0 + 1 + lane; j < e1; j += 32) {
        s0 += g_cee[j];
        s1 += g_cee[Etot + j];
        s2 += g_cee[2 * Etot + j];
    }
#pragma unroll
    for (int o = 16; o; o >>= 1) {
        s0 += __shfl_xor_sync(0xffffffffu, s0, o);
        s1 += __shfl_xor_sync(0xffffffffu, s1, o);
        s2 += __shfl_xor_sync(0xffffffffu, s2, o);
    }
    if (lane == 0) {
        float invd = 1.f / fmaxf((float)(e1 - e0 - 1), 1.f);
        g_csrc[e0] = node;
        g_cee[e0] = s0 * invd;
        g_cee[Etot + e0] = s1 * invd;
        g_cee[2 * Etot + e0] = s2 * invd;
    }
}

// ---------------------------------------------------------------------------
// Smem-free tf32 GEMM + fused scores; H stored as fp16.
template <int BN>
__global__ void __launch_bounds__(256, 2)
gemm_frag(const unsigned* __restrict__ Af, const unsigned* __restrict__ Wf,
          const float* __restrict__ as_, const float* __restrict__ ad_,
          __half* __restrict__ H, int M) {
    const int MI = (BN == 128) ? 2 : 1;
    const int RPW = (BN == 128) ? 32 : 16;
    __shared__ float Sp[512];
    int tid = threadIdx.x;
    int lane = tid & 31, wid = tid >> 5;
    int g = lane >> 2, tq = lane & 3;
    int wr = (BN == 128) ? (wid & 3) : wid;
    int wc = (BN == 128) ? (wid >> 2) : 0;
    int row0 = blockIdx.x * 128;

    float4 acc[MI][8];
#pragma unroll
    for (int mi = 0; mi < MI; mi++)
#pragma unroll
        for (int nt = 0; nt < 8; nt++) acc[mi][nt] = make_float4(0.f, 0.f, 0.f, 0.f);

    const unsigned* pa[MI][2];
#pragma unroll
    for (int mi = 0; mi < MI; mi++) {
        int rb = row0 + wr * RPW + mi * 16;
        pa[mi][0] = Af + (size_t)(rb + g) * 128 + tq * 2;
        pa[mi][1] = Af + (size_t)(rb + g + 8) * 128 + tq * 2;
    }
    const unsigned* pb = Wf + ((size_t)(wc * 8) * 16 * 32 + lane) * 2;

#pragma unroll
    for (int kb = 0; kb < 16; kb++) {
        uint2 au[MI], av[MI];
#pragma unroll
        for (int mi = 0; mi < MI; mi++) {
            au[mi] = *(const uint2*)(pa[mi][0] + kb * 8);
            av[mi] = *(const uint2*)(pa[mi][1] + kb * 8);
        }
#pragma unroll
        for (int nt = 0; nt < 8; nt++) {
            uint2 b = *(const uint2*)(pb + (nt * 16 + kb) * 64);
#pragma unroll
            for (int mi = 0; mi < MI; mi++)
                mma_k8(acc[mi][nt], au[mi].x, av[mi].x, au[mi].y, av[mi].y,
                       b.x, b.y);
        }
    }

    float s1l[MI], s2l[MI], s1h[MI], s2h[MI];
#pragma unroll
    for (int mi = 0; mi < MI; mi++) { s1l[mi]=s2l[mi]=s1h[mi]=s2h[mi]=0.f; }
#pragma unroll
    for (int mi = 0; mi < MI; mi++) {
        int rA = row0 + wr * RPW + mi * 16 + g;
#pragma unroll
        for (int nt = 0; nt < 8; nt++) {
            int c0 = wc * 64 + nt * 8 + 2 * tq;
            float w1 = as_[c0], w1b = as_[c0 + 1];
            float w2 = ad_[c0], w2b = ad_[c0 + 1];
            float4 c = acc[mi][nt];
            s1l[mi] += c.x * w1 + c.y * w1b;
            s2l[mi] += c.x * w2 + c.y * w2b;
            s1h[mi] += c.z * w1 + c.w * w1b;
            s2h[mi] += c.z * w2 + c.w * w2b;
            if (rA < M)
                *(__half2*)&H[(size_t)rA * BN + c0] = __floats2half2_rn(c.x, c.y);
            if (rA + 8 < M)
                *(__half2*)&H[(size_t)(rA + 8) * BN + c0] = __floats2half2_rn(c.z, c.w);
        }
    }
#pragma unroll
    for (int mi = 0; mi < MI; mi++) {
#pragma unroll
        for (int o = 1; o < 4; o <<= 1) {
            s1l[mi] += __shfl_xor_sync(0xffffffffu, s1l[mi], o);
            s2l[mi] += __shfl_xor_sync(0xffffffffu, s2l[mi], o);
            s1h[mi] += __shfl_xor_sync(0xffffffffu, s1h[mi], o);
            s2h[mi] += __shfl_xor_sync(0xffffffffu, s2h[mi], o);
        }
    }
    if (BN == 64) {
        if (tq == 0) {
            int rA = row0 + wr * RPW + g;
            if (rA < M)     { g_ss[rA] = s1l[0];     g_sd[rA] = s2l[0]; }
            if (rA + 8 < M) { g_ss[rA + 8] = s1h[0]; g_sd[rA + 8] = s2h[0]; }
        }
    } else {
        if (tq == 0) {
#pragma unroll
            for (int mi = 0; mi < MI; mi++) {
                int rib = wr * RPW + mi * 16 + g;
                Sp[wc * 128 + rib]           = s1l[mi];
                Sp[wc * 128 + rib + 8]       = s1h[mi];
                Sp[256 + wc * 128 + rib]     = s2l[mi];
                Sp[256 + wc * 128 + rib + 8] = s2h[mi];
            }
        }
        __syncthreads();
        if (tid < 128) {
            int r = row0 + tid;
            if (r < M) {
                g_ss[r] = Sp[tid] + Sp[128 + tid];
                g_sd[r] = Sp[256 + tid] + Sp[384 + tid];
            }
        }
    }
}

// ---------------------------------------------------------------------------
// Warp-per-dst online softmax + aggregation, fp16 gather (8B/lane),
// frag-layout tf32 output for the next GEMM.
__global__ void aggregate128(int layer, int Etot, const float* __restrict__ bias,
                             unsigned* __restrict__ outf, int n) {
    const float* cee = g_cee + (size_t)layer * Etot;
    int node = blockIdx.x * (blockDim.x >> 5) + (threadIdx.x >> 5);
    int lane = threadIdx.x & 31;
    if (node >= n) return;
    int e0 = g_off[node], e1 = g_off[node + 1];
    float sdn = g_sd[node];

    float m = -INFINITY, denom = 0.f;
    float4 acc = make_float4(0.f, 0.f, 0.f, 0.f);

    for (int jb = e0; jb < e1; jb += 32) {
        int j = jb + lane;
        float a = -INFINITY;
        int s = 0;
        if (j < e1) {
            s = g_csrc[j];
            a = g_ss[s] + sdn + cee[j];
            a = (a > 0.f) ? a : 0.2f * a;
        }
        float bm = a;
#pragma unroll
        for (int o = 16; o; o >>= 1) bm = fmaxf(bm, __shfl_xor_sync(0xffffffffu, bm, o));
        float newm = fmaxf(m, bm);
        float scale = __expf(m - newm);
        denom *= scale;
        acc.x *= scale; acc.y *= scale; acc.z *= scale; acc.w *= scale;
        m = newm;
        float ex = (j < e1) ? __expf(a - m) : 0.f;
        denom += ex;
        int cnt = min(32, e1 - jb);
        int k = 0;
        for (; k + 8 <= cnt; k += 8) {
            float ef[8]; int sv[8];
#pragma unroll
            for (int q = 0; q < 8; q++) {
                ef[q] = __shfl_sync(0xffffffffu, ex, k + q);
                sv[q] = __shfl_sync(0xffffffffu, s, k + q);
            }
            __half2 hv[8][2];
#pragma unroll
            for (int q = 0; q < 8; q++) {
                const __half2* hp = (const __half2*)(g_h + (size_t)sv[q] * 128) + lane * 2;
                hv[q][0] = hp[0]; hv[q][1] = hp[1];
            }
#pragma unroll
            for (int q = 0; q < 8; q++) {
                float2 lo = __half22float2(hv[q][0]);
                float2 hi = __half22float2(hv[q][1]);
                acc.x += ef[q] * lo.x; acc.y += ef[q] * lo.y;
                acc.z += ef[q] * hi.x; acc.w += ef[q] * hi.y;
            }
        }
        for (; k < cnt; k++) {
            float exk = __shfl_sync(0xffffffffu, ex, k);
            int sk = __shfl_sync(0xffffffffu, s, k);
            const __half2* hp = (const __half2*)(g_h + (size_t)sk * 128) + lane * 2;
            float2 lo = __half22float2(hp[0]);
            float2 hi = __half22float2(hp[1]);
            acc.x += exk * lo.x; acc.y += exk * lo.y;
            acc.z += exk * hi.x; acc.w += exk * hi.y;
        }
    }
#pragma unroll
    for (int o = 16; o; o >>= 1) denom += __shfl_xor_sync(0xffffffffu, denom, o);
    float inv = 1.f / (denom + 1e-16f);
    float4 b = *(const float4*)(bias + lane * 4);
    float4 r;
    r.x = fmaxf(acc.x * inv + b.x, 0.f);
    r.y = fmaxf(acc.y * inv + b.y, 0.f);
    r.z = fmaxf(acc.z * inv + b.z, 0.f);
    r.w = fmaxf(acc.w * inv + b.w, 0.f);
    unsigned* base = outf + (size_t)node * 128 + (lane >> 1) * 8 + (lane & 1);
    base[0] = f2tf32(r.x); base[2] = f2tf32(r.y);
    base[4] = f2tf32(r.z); base[6] = f2tf32(r.w);
}

// Final layer (C=64): fp16 gather, fp32 row-major output, no relu.
__global__ void aggregate64(int layer, int Etot, const float* __restrict__ bias,
                            float* __restrict__ out, int n) {
    const float* cee = g_cee + (size_t)layer * Etot;
    int node = blockIdx.x * (blockDim.x >> 5) + (threadIdx.x >> 5);
    int lane = threadIdx.x & 31;
    if (node >= n) return;
    int e0 = g_off[node], e1 = g_off[node + 1];
    float sdn = g_sd[node];

    float m = -INFINITY, denom = 0.f;
    float2 acc = make_float2(0.f, 0.f);

    for (int jb = e0; jb < e1; jb += 32) {
        int j = jb + lane;
        float a = -INFINITY;
        int s = 0;
        if (j < e1) {
            s = g_csrc[j];
            a = g_ss[s] + sdn + cee[j];
            a = (a > 0.f) ? a : 0.2f * a;
        }
        float bm = a;
#pragma unroll
        for (int o = 16; o; o >>= 1) bm = fmaxf(bm, __shfl_xor_sync(0xffffffffu, bm, o));
        float newm = fmaxf(m, bm);
        float scale = __expf(m - newm);
        denom *= scale;
        acc.x *= scale; acc.y *= scale;
        m = newm;
        float ex = (j < e1) ? __expf(a - m) : 0.f;
        denom += ex;
        int cnt = min(32, e1 - jb);
        int k = 0;
        for (; k + 8 <= cnt; k += 8) {
            float ef[8]; int sv[8];
#pragma unroll
            for (int q = 0; q < 8; q++) {
                ef[q] = __shfl_sync(0xffffffffu, ex, k + q);
                sv[q] = __shfl_sync(0xffffffffu, s, k + q);
            }
            __half2 hv[8];
#pragma unroll
            for (int q = 0; q < 8; q++)
                hv[q] = *((const __half2*)(g_h + (size_t)sv[q] * 64) + lane);
#pragma unroll
            for (int q = 0; q < 8; q++) {
                float2 lo = __half22float2(hv[q]);
                acc.x += ef[q] * lo.x; acc.y += ef[q] * lo.y;
            }
        }
        for (; k < cnt; k++) {
            float exk = __shfl_sync(0xffffffffu, ex, k);
            int sk = __shfl_sync(0xffffffffu, s, k);
            float2 lo = __half22float2(*((const __half2*)(g_h + (size_t)sk * 64) + lane));
            acc.x += exk * lo.x; acc.y += exk * lo.y;
        }
    }
#pragma unroll
    for (int o = 16; o; o >>= 1) denom += __shfl_xor_sync(0xffffffffu, denom, o);
    float inv = 1.f / (denom + 1e-16f);
    float2 b = *(const float2*)(bias + lane * 2);
    float2 r;
    r.x = acc.x * inv + b.x;
    r.y = acc.y * inv + b.y;
    *(float2*)(out + (size_t)node * 64 + lane * 2) = r;
}

extern "C" void kernel_launch(void* const* d_in, const int* in_sizes, int n_in,
                              void* d_out, int out_size) {
    const float* x      = (const float*)d_in[0];
    const void*  ei     = d_in[1];
    const float* ea     = (const float*)d_in[2];
    const float* W[3]  = {(const float*)d_in[3],  (const float*)d_in[9],  (const float*)d_in[15]};
    const float* As_[3]= {(const float*)d_in[4],  (const float*)d_in[10], (const float*)d_in[16]};
    const float* Ad[3] = {(const float*)d_in[5],  (const float*)d_in[11], (const float*)d_in[17]};
    const float* We[3] = {(const float*)d_in[6],  (const float*)d_in[12], (const float*)d_in[18]};
    const float* Ae[3] = {(const float*)d_in[7],  (const float*)d_in[13], (const float*)d_in[19]};
    const float* Bb[3] = {(const float*)d_in[8],  (const float*)d_in[14], (const float*)d_in[20]};

    int N = in_sizes[0] / 128;
    int E = in_sizes[2] / 8;
    int Etot = E + N;
    int forced = (in_sizes[1] == 4 * E) ? 1 : -1;

    static __half* h = nullptr;
    static unsigned *xf = nullptr, *bufAf = nullptr, *bufBf = nullptr;
    static unsigned *wf0 = nullptr, *wf1 = nullptr, *wf2 = nullptr;
    if (!h) {
        cudaGetSymbolAddress((void**)&h,     g_h);
        cudaGetSymbolAddress((void**)&xf,    g_xf);
        cudaGetSymbolAddress((void**)&bufAf, g_bufAf);
        cudaGetSymbolAddress((void**)&bufBf, g_bufBf);
        cudaGetSymbolAddress((void**)&wf0,   g_wf0);
        cudaGetSymbolAddress((void**)&wf1,   g_wf1);
        cudaGetSymbolAddress((void**)&wf2,   g_wf2);
    }

    int gb = (N + 127) / 128;
    int nb = (N + 7) / 8;

    // 1: operand transforms; 2: init; 3: degree; 4: gemm0 (profiled slot)
    xform_kernel<<<(N * 32 + 40960 + 255) / 256, 256>>>(x, W[0], W[1], W[2], N);
    init_kernel<<<(N + 255) / 256, 256>>>((const int*)ei, forced,
                                          We[0], Ae[0], We[1], Ae[1], We[2], Ae[2], N);
    count_kernel<<<(E + 255) / 256, 256>>>(ei, E, N);
    gemm_frag<128><<<gb, 256>>>(xf, wf0, As_[0], Ad[0], h, N);
    // 5-7: CSR build
    scan_kernel<<<1, 1024>>>(N);
    edgefill_kernel<<<(E + 255) / 256, 256>>>(ea, ei, E, Etot, N);
    selfloop_kernel<<<nb, 256>>>(Etot, N);
    // 8-12: layers
    aggregate128<<<nb, 256>>>(0, Etot, Bb[0], bufAf, N);
    gemm_frag<128><<<gb, 256>>>(bufAf, wf1, As_[1], Ad[1], h, N);
    aggregate128<<<nb, 256>>>(1, Etot, Bb[1], bufBf, N);
    gemm_frag<64><<<gb, 256>>>(bufBf, wf2, As_[2], Ad[2], h, N);
    aggregate64<<<nb, 256>>>(2, Etot, Bb[2], (float*)d_out, N);
}